// round 8
// baseline (speedup 1.0000x reference)
#include <cuda_runtime.h>
#include <math.h>
#include <stdint.h>

// Problem constants (shapes fixed by the dataset)
#define NNODES 50000
#define NEDGES 800000
#define EETOT  (NNODES + NEDGES)
#define C64    64

// ---------------- scratch (static device globals; no allocation allowed) ---
__device__ __align__(256) float g_xl [NNODES * C64];
__device__ __align__(256) float g_xr [NNODES * C64];
__device__ __align__(256) float g_agg[NNODES * C64];
__device__ __align__(256) int   g_srcb[EETOT];      // CSR src ids (sorted by dst)
__device__ __align__(256) int   g_off [NNODES];     // CSR row offsets
__device__ __align__(256) int   g_deg [NNODES];     // in-degree per node
__device__ __align__(256) int   g_cur [NNODES];     // scatter cursors
__device__ __align__(256) int   g_order[NNODES];    // nodes sorted by degree
__device__ __align__(256) int   g_bsum[64];         // per-block degree sums
__device__ __align__(256) int   g_bofs[64];         // exclusive scan of bsum
__device__ __align__(256) int   g_dh  [256];        // degree histogram
__device__ __align__(256) int   g_dcur[256];        // degree-bucket cursors
__device__ __align__(256) float g_st [128];         // per-channel sum / sumsq
__device__ __align__(256) float g_bnp[128];         // BN scale / shift
__device__ int g_idx64;                              // 1 if edge_index is int64

// ---------------- helpers ---------------------------------------------------
__device__ __forceinline__ int load_idx(const void* ei, long long pos) {
    if (g_idx64) return (int)((const long long*)ei)[pos];
    return ((const int*)ei)[pos];
}

__device__ __forceinline__ float tf32r(float x) {
    uint32_t u;
    asm("cvt.rna.tf32.f32 %0, %1;" : "=r"(u) : "f"(x));
    return __uint_as_float(u);
}

#define MMA_TF32(d, a, b0, b1) \
    asm volatile("mma.sync.aligned.m16n8k8.row.col.f32.tf32.tf32.f32 " \
                 "{%0,%1,%2,%3}, {%4,%5,%6,%7}, {%8,%9}, {%0,%1,%2,%3};" \
                 : "+f"((d)[0]), "+f"((d)[1]), "+f"((d)[2]), "+f"((d)[3]) \
                 : "r"((a)[0]), "r"((a)[1]), "r"((a)[2]), "r"((a)[3]), \
                   "r"(b0), "r"(b1))

// zero deg + degree-histogram bins; block 0 warp 0 detects int64 vs int32
__global__ void zero_detect_k(const int* ei32, int E,
                              int* __restrict__ deg, int* __restrict__ dh,
                              int N) {
    int i = blockIdx.x * blockDim.x + threadIdx.x;
    if (i < N) deg[i] = 0;
    if (i < 256) dh[i] = 0;
    if (blockIdx.x == 0 && threadIdx.x < 32) {
        int t = threadIdx.x;
        int nz = 0;
        if (2 * t + 1 < 2 * E)        nz |= (ei32[2 * t + 1] != 0);
        if (2 * (t + 32) + 1 < 2 * E) nz |= (ei32[2 * (t + 32) + 1] != 0);
        nz = __any_sync(0xffffffffu, nz);
        if (t == 0) g_idx64 = nz ? 0 : 1;
    }
}

// ---------------- CSR build: histogram, 3-stage scan, scatter ---------------
__global__ void hist_k(const void* __restrict__ ei, int* __restrict__ deg,
                       int E, int EE) {
    int i = blockIdx.x * blockDim.x + threadIdx.x;
    if (i >= EE) return;
    int dst = (i < E) ? load_idx(ei, (long long)E + i) : i - E;
    atomicAdd(&deg[dst], 1);
}

// degree histogram (256 bins, clamped)
__global__ void dhist_k(const int* __restrict__ deg, int* __restrict__ dh,
                        int N) {
    int i = blockIdx.x * blockDim.x + threadIdx.x;
    if (i >= N) return;
    int b = min(deg[i], 255);
    atomicAdd(&dh[b], 1);
}

// per-block (1024 nodes) degree sums
__global__ void blocksum_k(const int* __restrict__ deg, int* __restrict__ bsum,
                           int N) {
    __shared__ int ws[8];
    int t = threadIdx.x;                 // 256
    int i0 = blockIdx.x * 1024 + t * 4;
    int s = 0;
    if (i0 + 3 < N) {
        int4 v = *(const int4*)&deg[i0];
        s = v.x + v.y + v.z + v.w;
    } else {
        for (int j = 0; j < 4; ++j) if (i0 + j < N) s += deg[i0 + j];
    }
#pragma unroll
    for (int o = 16; o; o >>= 1) s += __shfl_down_sync(0xffffffffu, s, o);
    if ((t & 31) == 0) ws[t >> 5] = s;
    __syncthreads();
    if (t == 0) {
        int tot = 0;
#pragma unroll
        for (int i = 0; i < 8; ++i) tot += ws[i];
        bsum[blockIdx.x] = tot;
    }
}

// exclusive scan of ≤64 block sums + 256-bin degree-hist scan; zero BN stats
__global__ void topscan_k(const int* __restrict__ bsum, int* __restrict__ bofs,
                          float* __restrict__ st,
                          const int* __restrict__ dh, int* __restrict__ dcur,
                          int nb) {
    __shared__ int sh[64];
    __shared__ int wsum[8];
    int t = threadIdx.x;                 // 256
    int lane = t & 31, warp = t >> 5;
    if (t < 128) st[t] = 0.f;

    int vb = 0;
    if (t < 64) {
        vb = (t < nb) ? bsum[t] : 0;
        int inc = vb;
#pragma unroll
        for (int o = 1; o < 32; o <<= 1) {
            int u = __shfl_up_sync(0xffffffffu, inc, o);
            if (lane >= o) inc += u;
        }
        sh[t] = inc;
    }

    int v = dh[t];
    int inc = v;
#pragma unroll
    for (int o = 1; o < 32; o <<= 1) {
        int u = __shfl_up_sync(0xffffffffu, inc, o);
        if (lane >= o) inc += u;
    }
    if (lane == 31) wsum[warp] = inc;
    __syncthreads();

    if (t < 64) {
        int add = (t >= 32) ? sh[31] : 0;
        bofs[t] = sh[t] + add - vb;
    }
    int wofs = 0;
#pragma unroll
    for (int wi = 0; wi < 8; ++wi) if (wi < warp) wofs += wsum[wi];
    dcur[t] = wofs + inc - v;
}

// per-block fill of off/cur via hierarchical scan
__global__ void fill_k(const int* __restrict__ deg, const int* __restrict__ bofs,
                       int* __restrict__ off, int* __restrict__ cur, int N) {
    __shared__ int wsum[8];
    int t = threadIdx.x, lane = t & 31, warp = t >> 5;
    int i0 = blockIdx.x * 1024 + t * 4;
    int d0 = 0, d1 = 0, d2 = 0, d3 = 0;
    if (i0 + 3 < N) {
        int4 v = *(const int4*)&deg[i0];
        d0 = v.x; d1 = v.y; d2 = v.z; d3 = v.w;
    } else {
        if (i0     < N) d0 = deg[i0];
        if (i0 + 1 < N) d1 = deg[i0 + 1];
        if (i0 + 2 < N) d2 = deg[i0 + 2];
    }
    int tsum = d0 + d1 + d2 + d3;
    int inc = tsum;
#pragma unroll
    for (int o = 1; o < 32; o <<= 1) {
        int u = __shfl_up_sync(0xffffffffu, inc, o);
        if (lane >= o) inc += u;
    }
    if (lane == 31) wsum[warp] = inc;
    __syncthreads();
    int wofs = 0;
#pragma unroll
    for (int wi = 0; wi < 8; ++wi) if (wi < warp) wofs += wsum[wi];
    int base = bofs[blockIdx.x] + wofs + inc - tsum;
    int o0 = base, o1 = o0 + d0, o2 = o1 + d1, o3 = o2 + d2;
    if (i0 + 3 < N) {
        *(int4*)&off[i0] = make_int4(o0, o1, o2, o3);
        *(int4*)&cur[i0] = make_int4(o0, o1, o2, o3);
    } else {
        if (i0     < N) { off[i0]     = o0; cur[i0]     = o0; }
        if (i0 + 1 < N) { off[i0 + 1] = o1; cur[i0 + 1] = o1; }
        if (i0 + 2 < N) { off[i0 + 2] = o2; cur[i0 + 2] = o2; }
    }
}

// scatter nodes into degree-sorted order
__global__ void dorder_k(const int* __restrict__ deg, int* __restrict__ dcur,
                         int* __restrict__ order, int N) {
    int i = blockIdx.x * blockDim.x + threadIdx.x;
    if (i >= N) return;
    int b = min(deg[i], 255);
    int pos = atomicAdd(&dcur[b], 1);
    order[pos] = i;
}

__global__ void scatter_k(const void* __restrict__ ei, int* __restrict__ cur,
                          int* __restrict__ srcb, int E, int EE) {
    int i = blockIdx.x * blockDim.x + threadIdx.x;
    if (i >= EE) return;
    int src, dst;
    if (i < E) { src = load_idx(ei, i); dst = load_idx(ei, (long long)E + i); }
    else       { src = dst = i - E; }
    int pos = atomicAdd(&cur[dst], 1);
    srcb[pos] = src;
}

// ---------------- dual GEMM via tf32x3 tensor cores -------------------------
#define KC 16
__global__ void __launch_bounds__(256)
gemm_tf32(const float* __restrict__ A,
          const float* __restrict__ W0,
          const float* __restrict__ W1,
          const float* __restrict__ bnp,   // null = no BN
          float* __restrict__ O0, float* __restrict__ O1,
          int M, int K) {
    __shared__ uint32_t Ah[KC][136], Al[KC][136];
    __shared__ uint32_t Wh[KC][136], Wl[KC][136];
    const int t = threadIdx.x;
    const int lane = t & 31, warp = t >> 5;
    const int wm = warp >> 1, wn = warp & 1;
    const int g = lane >> 2, c = lane & 3;
    const int row0 = blockIdx.x * 128;
    const int rbase = wm * 32;
    const int nbase0 = wn * 64;

    float d[2][8][4];
#pragma unroll
    for (int i = 0; i < 2; ++i)
#pragma unroll
        for (int j = 0; j < 8; ++j)
#pragma unroll
            for (int q = 0; q < 4; ++q) d[i][j][q] = 0.f;

    const int nchunk = K / KC;
    for (int ch = 0; ch < nchunk; ++ch) {
        const int k0 = ch * KC;
        __syncthreads();
#pragma unroll
        for (int i = 0; i < 2; ++i) {
            int l = t + 256 * i;
            int r = l >> 2, kq = (l & 3) * 4;
            float4 v = make_float4(0.f, 0.f, 0.f, 0.f);
            if (row0 + r < M)
                v = *(const float4*)&A[(size_t)(row0 + r) * K + k0 + kq];
            if (bnp) {
                float4 sc = *(const float4*)&bnp[k0 + kq];
                float4 sh = *(const float4*)&bnp[64 + k0 + kq];
                v.x = fmaxf(v.x * sc.x + sh.x, 0.f);
                v.y = fmaxf(v.y * sc.y + sh.y, 0.f);
                v.z = fmaxf(v.z * sc.z + sh.z, 0.f);
                v.w = fmaxf(v.w * sc.w + sh.w, 0.f);
            }
            float vv[4] = {v.x, v.y, v.z, v.w};
#pragma unroll
            for (int j = 0; j < 4; ++j) {
                float hi = tf32r(vv[j]);
                float lo = tf32r(vv[j] - hi);
                Ah[kq + j][r] = __float_as_uint(hi);
                Al[kq + j][r] = __float_as_uint(lo);
            }
        }
#pragma unroll
        for (int i = 0; i < 2; ++i) {
            int l = t + 256 * i;
            int kk = l >> 5, col = (l & 31) * 4;
            const float* src = (col < 64)
                ? &W0[(size_t)(k0 + kk) * 64 + col]
                : &W1[(size_t)(k0 + kk) * 64 + (col - 64)];
            float4 v = *(const float4*)src;
            float vv[4] = {v.x, v.y, v.z, v.w};
#pragma unroll
            for (int j = 0; j < 4; ++j) {
                float hi = tf32r(vv[j]);
                float lo = tf32r(vv[j] - hi);
                Wh[kk][col + j] = __float_as_uint(hi);
                Wl[kk][col + j] = __float_as_uint(lo);
            }
        }
        __syncthreads();

#pragma unroll
        for (int ks = 0; ks < KC / 8; ++ks) {
            const int kb = ks * 8;
            uint32_t ah[2][4], al[2][4];
#pragma unroll
            for (int mt = 0; mt < 2; ++mt) {
                int r = rbase + mt * 16 + g;
                ah[mt][0] = Ah[kb + c][r];     ah[mt][1] = Ah[kb + c][r + 8];
                ah[mt][2] = Ah[kb + c + 4][r]; ah[mt][3] = Ah[kb + c + 4][r + 8];
                al[mt][0] = Al[kb + c][r];     al[mt][1] = Al[kb + c][r + 8];
                al[mt][2] = Al[kb + c + 4][r]; al[mt][3] = Al[kb + c + 4][r + 8];
            }
#pragma unroll
            for (int nt = 0; nt < 8; ++nt) {
                int n = nbase0 + nt * 8 + g;
                uint32_t bh0 = Wh[kb + c][n],     bh1 = Wh[kb + c + 4][n];
                uint32_t bl0 = Wl[kb + c][n],     bl1 = Wl[kb + c + 4][n];
#pragma unroll
                for (int mt = 0; mt < 2; ++mt) {
                    MMA_TF32(d[mt][nt], ah[mt], bh0, bh1);
                    MMA_TF32(d[mt][nt], ah[mt], bl0, bl1);
                    MMA_TF32(d[mt][nt], al[mt], bh0, bh1);
                }
            }
        }
    }

    float* O = (wn == 0) ? O0 : O1;
#pragma unroll
    for (int mt = 0; mt < 2; ++mt) {
#pragma unroll
        for (int nt = 0; nt < 8; ++nt) {
            int nn = nt * 8 + 2 * c;
            int r0w = row0 + rbase + mt * 16 + g;
            if (r0w < M)
                *(float2*)&O[(size_t)r0w * 64 + nn] =
                    make_float2(d[mt][nt][0], d[mt][nt][1]);
            int r1w = r0w + 8;
            if (r1w < M)
                *(float2*)&O[(size_t)r1w * 64 + nn] =
                    make_float2(d[mt][nt][2], d[mt][nt][3]);
        }
    }
}

// ---------------- fused GATv2 edge pass (node-parallel, online softmax) -----
// 4 lanes per dst node (degree-sorted order for warp balance); 2-wide,
// 2-deep software-pipelined edge loop. Group-mask butterfly (lanes of a
// group share trip count). Epilogue adds bias, writes agg, accumulates
// BN stats.
__global__ void gat_fused(const int* __restrict__ srcb,
                          const int* __restrict__ off,
                          const int* __restrict__ deg,
                          const int* __restrict__ order,
                          const float* __restrict__ xl,
                          const float* __restrict__ xr,
                          const float* __restrict__ att,
                          const float* __restrict__ bias,
                          float* __restrict__ agg,
                          float* __restrict__ st, int N) {
    __shared__ float ssum[64], ssq[64];
    const int t = threadIdx.x;
    int g = blockIdx.x * blockDim.x + t;
    int grp = g >> 2;
    int lane = g & 3;
    bool valid = grp < N;
    int nd = valid ? __ldg(&order[grp]) : 0;

    const unsigned gmask = 0xFu << ((t & 31) & ~3);

    if (t < 64) { ssum[t] = 0.f; ssq[t] = 0.f; }

    const float4* xr4 = (const float4*)(xr + (size_t)nd * 64) + lane * 4;
    float4 r0 = xr4[0], r1 = xr4[1], r2 = xr4[2], r3 = xr4[3];
    const float4* at4 = (const float4*)att + lane * 4;
    float4 a0 = at4[0], a1 = at4[1], a2 = at4[2], a3 = at4[3];

    int base = valid ? __ldg(&off[nd]) : 0;
    int cnt  = valid ? __ldg(&deg[nd]) : 0;

    float m = -1e30f, s = 0.f;
    float4 c0 = make_float4(0.f,0.f,0.f,0.f), c1 = c0, c2 = c0, c3 = c0;

#define LOADE(B0, B1, B2, B3, IDX) do { \
        int _s = __ldg(&srcb[base + (IDX)]); \
        const float4* _p = (const float4*)(xl + (size_t)_s * 64) + lane * 4; \
        B0 = _p[0]; B1 = _p[1]; B2 = _p[2]; B3 = _p[3]; } while(0)

#define PROC(L0, L1, L2, L3) do { \
        float e = 0.f, v; \
        v = L0.x + r0.x; e += a0.x * fmaxf(v, 0.2f * v); \
        v = L0.y + r0.y; e += a0.y * fmaxf(v, 0.2f * v); \
        v = L0.z + r0.z; e += a0.z * fmaxf(v, 0.2f * v); \
        v = L0.w + r0.w; e += a0.w * fmaxf(v, 0.2f * v); \
        v = L1.x + r1.x; e += a1.x * fmaxf(v, 0.2f * v); \
        v = L1.y + r1.y; e += a1.y * fmaxf(v, 0.2f * v); \
        v = L1.z + r1.z; e += a1.z * fmaxf(v, 0.2f * v); \
        v = L1.w + r1.w; e += a1.w * fmaxf(v, 0.2f * v); \
        v = L2.x + r2.x; e += a2.x * fmaxf(v, 0.2f * v); \
        v = L2.y + r2.y; e += a2.y * fmaxf(v, 0.2f * v); \
        v = L2.z + r2.z; e += a2.z * fmaxf(v, 0.2f * v); \
        v = L2.w + r2.w; e += a2.w * fmaxf(v, 0.2f * v); \
        v = L3.x + r3.x; e += a3.x * fmaxf(v, 0.2f * v); \
        v = L3.y + r3.y; e += a3.y * fmaxf(v, 0.2f * v); \
        v = L3.z + r3.z; e += a3.z * fmaxf(v, 0.2f * v); \
        v = L3.w + r3.w; e += a3.w * fmaxf(v, 0.2f * v); \
        e += __shfl_xor_sync(gmask, e, 1); \
        e += __shfl_xor_sync(gmask, e, 2); \
        float mn  = fmaxf(m, e); \
        float scv = __expf(m - mn); \
        float pv  = __expf(e - mn); \
        m = mn; s = s * scv + pv; \
        c0.x = c0.x * scv + pv * L0.x; c0.y = c0.y * scv + pv * L0.y; \
        c0.z = c0.z * scv + pv * L0.z; c0.w = c0.w * scv + pv * L0.w; \
        c1.x = c1.x * scv + pv * L1.x; c1.y = c1.y * scv + pv * L1.y; \
        c1.z = c1.z * scv + pv * L1.z; c1.w = c1.w * scv + pv * L1.w; \
        c2.x = c2.x * scv + pv * L2.x; c2.y = c2.y * scv + pv * L2.y; \
        c2.z = c2.z * scv + pv * L2.z; c2.w = c2.w * scv + pv * L2.w; \
        c3.x = c3.x * scv + pv * L3.x; c3.y = c3.y * scv + pv * L3.y; \
        c3.z = c3.z * scv + pv * L3.z; c3.w = c3.w * scv + pv * L3.w; } while(0)

    float4 p00, p01, p02, p03, p10, p11, p12, p13;
    if (cnt > 0) LOADE(p00, p01, p02, p03, 0);
    if (cnt > 1) LOADE(p10, p11, p12, p13, 1);

    int j = 0;
    for (; j + 2 <= cnt; j += 2) {
        float4 q00, q01, q02, q03, q10, q11, q12, q13;
        bool m2 = (j + 2 < cnt), m3 = (j + 3 < cnt);
        if (m2) LOADE(q00, q01, q02, q03, j + 2);
        if (m3) LOADE(q10, q11, q12, q13, j + 3);
        PROC(p00, p01, p02, p03);
        PROC(p10, p11, p12, p13);
        if (m2) { p00 = q00; p01 = q01; p02 = q02; p03 = q03; }
        if (m3) { p10 = q10; p11 = q11; p12 = q12; p13 = q13; }
    }
    if (j < cnt) PROC(p00, p01, p02, p03);
#undef LOADE
#undef PROC

    float inv = 1.f / (s + 1e-16f);
    const float4* bq = (const float4*)bias + lane * 4;
    float4 b0 = bq[0], b1 = bq[1], b2 = bq[2], b3 = bq[3];
    float x[16];
#define XQ(q, C, B) \
    x[4*q+0] = C.x * inv + B.x; x[4*q+1] = C.y * inv + B.y; \
    x[4*q+2] = C.z * inv + B.z; x[4*q+3] = C.w * inv + B.w;
    XQ(0, c0, b0) XQ(1, c1, b1) XQ(2, c2, b2) XQ(3, c3, b3)
#undef XQ

    if (valid) {
        float4* o = (float4*)(agg + (size_t)nd * 64) + lane * 4;
        o[0] = make_float4(x[0],  x[1],  x[2],  x[3]);
        o[1] = make_float4(x[4],  x[5],  x[6],  x[7]);
        o[2] = make_float4(x[8],  x[9],  x[10], x[11]);
        o[3] = make_float4(x[12], x[13], x[14], x[15]);
    }
    if (!valid) {
#pragma unroll
        for (int i = 0; i < 16; ++i) x[i] = 0.f;
    }

    __syncthreads();   // ssum/ssq zero-init visible
#pragma unroll
    for (int i = 0; i < 16; ++i) {
        float sv = x[i];
        float qv = x[i] * x[i];
        sv += __shfl_down_sync(0xffffffffu, sv, 16);
        sv += __shfl_down_sync(0xffffffffu, sv, 8);
        sv += __shfl_down_sync(0xffffffffu, sv, 4);
        qv += __shfl_down_sync(0xffffffffu, qv, 16);
        qv += __shfl_down_sync(0xffffffffu, qv, 8);
        qv += __shfl_down_sync(0xffffffffu, qv, 4);
        if ((t & 31) < 4) {
            int ch = lane * 16 + i;
            atomicAdd(&ssum[ch], sv);
            atomicAdd(&ssq[ch], qv);
        }
    }
    __syncthreads();
    if (t < 64) {
        atomicAdd(&st[t], ssum[t]);
        atomicAdd(&st[64 + t], ssq[t]);
    }
}

// ---------------- BN prep: st -> (scale, shift); zero st for next layer -----
__global__ void prep_bn(const float* __restrict__ st,
                        const float* __restrict__ gamma,
                        const float* __restrict__ beta,
                        float* __restrict__ bnp,
                        float* __restrict__ st_mut, int N) {
    int t = threadIdx.x;   // 128 threads, 1 block
    float scale = 0.f, shift = 0.f;
    if (t < 64) {
        float invN = 1.f / (float)N;
        float mu  = st[t] * invN;
        float var = st[64 + t] * invN - mu * mu;
        float rs  = rsqrtf(var + 1e-5f);
        scale = gamma[t] * rs;
        shift = beta[t] - mu * scale;
    }
    __syncthreads();       // reads done before zeroing
    if (t < 64) { bnp[t] = scale; bnp[64 + t] = shift; }
    st_mut[t] = 0.f;
}

// ---------------- final head: BN(no affine) on [:,:32], softplus [:,32:] ----
__global__ void final_k(const float* __restrict__ v,
                        const float* __restrict__ st,
                        float* __restrict__ out, int N) {
    int i = blockIdx.x * blockDim.x + threadIdx.x;
    if (i >= N * 64) return;
    int n = i >> 6, c = i & 63;
    float x = v[i];
    if (c < 32) {
        float invN = 1.f / (float)N;
        float mu = st[c] * invN;
        float var = st[64 + c] * invN - mu * mu;
        out[(size_t)n * 32 + c] = (x - mu) * rsqrtf(var + 1e-5f);
    } else {
        float sp = fmaxf(x, 0.f) + log1pf(expf(-fabsf(x)));
        out[(size_t)N * 32 + (size_t)n * 32 + (c - 32)] = sp;
    }
}

// ---------------- host launcher ---------------------------------------------
extern "C" void kernel_launch(void* const* d_in, const int* in_sizes, int n_in,
                              void* d_out, int out_size) {
    const float* x    = (const float*)d_in[0];
    const void*  ei   = d_in[1];
    const float* Wl1  = (const float*)d_in[2];
    const float* Wr1  = (const float*)d_in[3];
    const float* att1 = (const float*)d_in[4];
    const float* b1   = (const float*)d_in[5];
    const float* ga1  = (const float*)d_in[6];
    const float* be1  = (const float*)d_in[7];
    const float* Wl2  = (const float*)d_in[8];
    const float* Wr2  = (const float*)d_in[9];
    const float* att2 = (const float*)d_in[10];
    const float* b2   = (const float*)d_in[11];
    float* out = (float*)d_out;

    const int N  = in_sizes[0] / 128;   // 50000
    const int E  = in_sizes[1] / 2;     // 800000
    const int EE = E + N;               // + self loops

    float *p_xl, *p_xr, *p_agg, *p_st, *p_bnp;
    int *p_srcb, *p_off, *p_deg, *p_cur, *p_bsum, *p_bofs;
    int *p_dh, *p_dcur, *p_order;
    cudaGetSymbolAddress((void**)&p_xl,    g_xl);
    cudaGetSymbolAddress((void**)&p_xr,    g_xr);
    cudaGetSymbolAddress((void**)&p_agg,   g_agg);
    cudaGetSymbolAddress((void**)&p_st,    g_st);
    cudaGetSymbolAddress((void**)&p_bnp,   g_bnp);
    cudaGetSymbolAddress((void**)&p_srcb,  g_srcb);
    cudaGetSymbolAddress((void**)&p_off,   g_off);
    cudaGetSymbolAddress((void**)&p_deg,   g_deg);
    cudaGetSymbolAddress((void**)&p_cur,   g_cur);
    cudaGetSymbolAddress((void**)&p_bsum,  g_bsum);
    cudaGetSymbolAddress((void**)&p_bofs,  g_bofs);
    cudaGetSymbolAddress((void**)&p_dh,    g_dh);
    cudaGetSymbolAddress((void**)&p_dcur,  g_dcur);
    cudaGetSymbolAddress((void**)&p_order, g_order);

    const int TB = 256;
    const int gEdge  = (EE + TB - 1) / TB;
    const int gNode  = (N + TB - 1) / TB;
    const int gGemm  = (N + 127) / 128;
    const int gFuse  = (N * 4 + TB - 1) / TB;
    const int gElem  = (N * 64 + TB - 1) / TB;
    const int gScan  = (N + 1023) / 1024;     // 49 blocks

    // ---- CSR build + degree sort (shared by both layers) ----
    zero_detect_k<<<gNode, TB>>>((const int*)ei, E, p_deg, p_dh, N);
    hist_k<<<gEdge, TB>>>(ei, p_deg, E, EE);
    dhist_k<<<gNode, TB>>>(p_deg, p_dh, N);
    blocksum_k<<<gScan, TB>>>(p_deg, p_bsum, N);
    topscan_k<<<1, 256>>>(p_bsum, p_bofs, p_st, p_dh, p_dcur, gScan);
    fill_k<<<gScan, TB>>>(p_deg, p_bofs, p_off, p_cur, N);
    dorder_k<<<gNode, TB>>>(p_deg, p_dcur, p_order, N);
    scatter_k<<<gEdge, TB>>>(ei, p_cur, p_srcb, E, EE);

    // ---- layer 1 ----
    gemm_tf32<<<gGemm, TB>>>(x, Wl1, Wr1, nullptr, p_xl, p_xr, N, 128);
    gat_fused<<<gFuse, TB>>>(p_srcb, p_off, p_deg, p_order, p_xl, p_xr,
                             att1, b1, p_agg, p_st, N);
    prep_bn<<<1, 128>>>(p_st, ga1, be1, p_bnp, p_st, N);

    // ---- layer 2 (BN+ReLU fused into gemm A-staging) ----
    gemm_tf32<<<gGemm, TB>>>(p_agg, Wl2, Wr2, p_bnp, p_xl, p_xr, N, 64);
    gat_fused<<<gFuse, TB>>>(p_srcb, p_off, p_deg, p_order, p_xl, p_xr,
                             att2, b2, p_agg, p_st, N);
    final_k<<<gElem, TB>>>(p_agg, p_st, out, N);
}

// round 9
// speedup vs baseline: 1.1719x; 1.1719x over previous
#include <cuda_runtime.h>
#include <math.h>
#include <stdint.h>

// Problem constants (shapes fixed by the dataset)
#define NNODES 50000
#define NEDGES 800000
#define EETOT  (NNODES + NEDGES)
#define C64    64

// ---------------- scratch (static device globals; no allocation allowed) ---
__device__ __align__(256) float g_xl [NNODES * C64];
__device__ __align__(256) float g_xr [NNODES * C64];
__device__ __align__(256) float g_agg[NNODES * C64];
__device__ __align__(256) int   g_srcb[EETOT];      // CSR src ids (sorted by dst)
__device__ __align__(256) int   g_off [NNODES];     // CSR row offsets
__device__ __align__(256) int   g_deg [NNODES];     // in-degree per node
__device__ __align__(256) int   g_cur [NNODES];     // scatter cursors
__device__ __align__(256) int   g_bsum[64];         // per-block degree sums
__device__ __align__(256) int   g_bofs[64];         // exclusive scan of bsum
__device__ __align__(256) float g_st [128];         // per-channel sum / sumsq
__device__ __align__(256) float g_bnp[128];         // BN scale / shift
__device__ int g_idx64;                              // 1 if edge_index is int64

// ---------------- helpers ---------------------------------------------------
__device__ __forceinline__ int load_idx(const void* ei, long long pos) {
    if (g_idx64) return (int)((const long long*)ei)[pos];
    return ((const int*)ei)[pos];
}

__device__ __forceinline__ float tf32r(float x) {
    uint32_t u;
    asm("cvt.rna.tf32.f32 %0, %1;" : "=r"(u) : "f"(x));
    return __uint_as_float(u);
}

#define MMA_TF32(d, a, b0, b1) \
    asm volatile("mma.sync.aligned.m16n8k8.row.col.f32.tf32.tf32.f32 " \
                 "{%0,%1,%2,%3}, {%4,%5,%6,%7}, {%8,%9}, {%0,%1,%2,%3};" \
                 : "+f"((d)[0]), "+f"((d)[1]), "+f"((d)[2]), "+f"((d)[3]) \
                 : "r"((a)[0]), "r"((a)[1]), "r"((a)[2]), "r"((a)[3]), \
                   "r"(b0), "r"(b1))

__global__ void detect_k(const int* ei32, int E) {
    int t = threadIdx.x;  // 32 threads
    int nz = 0;
    if (2 * t + 1 < 2 * E)        nz |= (ei32[2 * t + 1] != 0);
    if (2 * (t + 32) + 1 < 2 * E) nz |= (ei32[2 * (t + 32) + 1] != 0);
    nz = __any_sync(0xffffffffu, nz);
    if (t == 0) g_idx64 = nz ? 0 : 1;
}

// ---------------- CSR build: histogram, 3-stage scan, scatter ---------------
__global__ void hist_k(const void* __restrict__ ei, int* __restrict__ deg,
                       int E, int EE) {
    int i = blockIdx.x * blockDim.x + threadIdx.x;
    if (i >= EE) return;
    int dst = (i < E) ? load_idx(ei, (long long)E + i) : i - E;
    atomicAdd(&deg[dst], 1);
}

// per-block (1024 nodes) degree sums
__global__ void blocksum_k(const int* __restrict__ deg, int* __restrict__ bsum,
                           int N) {
    __shared__ int ws[8];
    int t = threadIdx.x;                 // 256
    int i0 = blockIdx.x * 1024 + t * 4;
    int s = 0;
    if (i0 + 3 < N) {
        int4 v = *(const int4*)&deg[i0];
        s = v.x + v.y + v.z + v.w;
    } else {
        for (int j = 0; j < 4; ++j) if (i0 + j < N) s += deg[i0 + j];
    }
#pragma unroll
    for (int o = 16; o; o >>= 1) s += __shfl_down_sync(0xffffffffu, s, o);
    if ((t & 31) == 0) ws[t >> 5] = s;
    __syncthreads();
    if (t == 0) {
        int tot = 0;
#pragma unroll
        for (int i = 0; i < 8; ++i) tot += ws[i];
        bsum[blockIdx.x] = tot;
    }
}

// exclusive scan of ≤64 block sums; also zero BN stats for layer 1
__global__ void topscan_k(const int* __restrict__ bsum, int* __restrict__ bofs,
                          float* __restrict__ st, int nb) {
    int t = threadIdx.x;                 // 128
    st[t] = 0.f;
    __shared__ int sh[64];
    if (t < 64) {
        int lane = t & 31;
        int v = (t < nb) ? bsum[t] : 0;
        int inc = v;
#pragma unroll
        for (int o = 1; o < 32; o <<= 1) {
            int u = __shfl_up_sync(0xffffffffu, inc, o);
            if (lane >= o) inc += u;
        }
        sh[t] = inc;
    }
    __syncthreads();
    if (t < 64) {
        int add = (t >= 32) ? sh[31] : 0;
        int inc = sh[t] + add;
        int v = (t < nb) ? bsum[t] : 0;
        bofs[t] = inc - v;
    }
}

// per-block fill of off/cur via hierarchical scan
__global__ void fill_k(const int* __restrict__ deg, const int* __restrict__ bofs,
                       int* __restrict__ off, int* __restrict__ cur, int N) {
    __shared__ int wsum[8];
    int t = threadIdx.x, lane = t & 31, warp = t >> 5;
    int i0 = blockIdx.x * 1024 + t * 4;
    int d0 = 0, d1 = 0, d2 = 0, d3 = 0;
    if (i0 + 3 < N) {
        int4 v = *(const int4*)&deg[i0];
        d0 = v.x; d1 = v.y; d2 = v.z; d3 = v.w;
    } else {
        if (i0     < N) d0 = deg[i0];
        if (i0 + 1 < N) d1 = deg[i0 + 1];
        if (i0 + 2 < N) d2 = deg[i0 + 2];
    }
    int tsum = d0 + d1 + d2 + d3;
    int inc = tsum;
#pragma unroll
    for (int o = 1; o < 32; o <<= 1) {
        int u = __shfl_up_sync(0xffffffffu, inc, o);
        if (lane >= o) inc += u;
    }
    if (lane == 31) wsum[warp] = inc;
    __syncthreads();
    int wofs = 0;
#pragma unroll
    for (int wi = 0; wi < 8; ++wi) if (wi < warp) wofs += wsum[wi];
    int base = bofs[blockIdx.x] + wofs + inc - tsum;
    int o0 = base, o1 = o0 + d0, o2 = o1 + d1, o3 = o2 + d2;
    if (i0 + 3 < N) {
        *(int4*)&off[i0] = make_int4(o0, o1, o2, o3);
        *(int4*)&cur[i0] = make_int4(o0, o1, o2, o3);
    } else {
        if (i0     < N) { off[i0]     = o0; cur[i0]     = o0; }
        if (i0 + 1 < N) { off[i0 + 1] = o1; cur[i0 + 1] = o1; }
        if (i0 + 2 < N) { off[i0 + 2] = o2; cur[i0 + 2] = o2; }
    }
}

__global__ void scatter_k(const void* __restrict__ ei, int* __restrict__ cur,
                          int* __restrict__ srcb, int E, int EE) {
    int i = blockIdx.x * blockDim.x + threadIdx.x;
    if (i >= EE) return;
    int src, dst;
    if (i < E) { src = load_idx(ei, i); dst = load_idx(ei, (long long)E + i); }
    else       { src = dst = i - E; }
    int pos = atomicAdd(&cur[dst], 1);
    srcb[pos] = src;
}

// ---------------- dual GEMM via tf32x3 tensor cores -------------------------
// O0 = A @ W0, O1 = A @ W1.  A: M x K, W: K x 64 row-major.
// 128x128 block tile, 8 warps: 4(m) x 2(n), each warp 32x64 = 2x8 m16n8k8.
// Operands split hi/lo (tf32x3): error ~O(eps_tf32^2).
// Optional fused BN+ReLU on A during staging.
#define KC 16
__global__ void __launch_bounds__(256)
gemm_tf32(const float* __restrict__ A,
          const float* __restrict__ W0,
          const float* __restrict__ W1,
          const float* __restrict__ bnp,   // null = no BN
          float* __restrict__ O0, float* __restrict__ O1,
          int M, int K) {
    __shared__ uint32_t Ah[KC][136], Al[KC][136];
    __shared__ uint32_t Wh[KC][136], Wl[KC][136];
    const int t = threadIdx.x;
    const int lane = t & 31, warp = t >> 5;
    const int wm = warp >> 1, wn = warp & 1;
    const int g = lane >> 2, c = lane & 3;
    const int row0 = blockIdx.x * 128;
    const int rbase = wm * 32;
    const int nbase0 = wn * 64;

    float d[2][8][4];
#pragma unroll
    for (int i = 0; i < 2; ++i)
#pragma unroll
        for (int j = 0; j < 8; ++j)
#pragma unroll
            for (int q = 0; q < 4; ++q) d[i][j][q] = 0.f;

    const int nchunk = K / KC;
    for (int ch = 0; ch < nchunk; ++ch) {
        const int k0 = ch * KC;
        __syncthreads();
#pragma unroll
        for (int i = 0; i < 2; ++i) {
            int l = t + 256 * i;
            int r = l >> 2, kq = (l & 3) * 4;
            float4 v = make_float4(0.f, 0.f, 0.f, 0.f);
            if (row0 + r < M)
                v = *(const float4*)&A[(size_t)(row0 + r) * K + k0 + kq];
            if (bnp) {
                float4 sc = *(const float4*)&bnp[k0 + kq];
                float4 sh = *(const float4*)&bnp[64 + k0 + kq];
                v.x = fmaxf(v.x * sc.x + sh.x, 0.f);
                v.y = fmaxf(v.y * sc.y + sh.y, 0.f);
                v.z = fmaxf(v.z * sc.z + sh.z, 0.f);
                v.w = fmaxf(v.w * sc.w + sh.w, 0.f);
            }
            float vv[4] = {v.x, v.y, v.z, v.w};
#pragma unroll
            for (int j = 0; j < 4; ++j) {
                float hi = tf32r(vv[j]);
                float lo = tf32r(vv[j] - hi);
                Ah[kq + j][r] = __float_as_uint(hi);
                Al[kq + j][r] = __float_as_uint(lo);
            }
        }
#pragma unroll
        for (int i = 0; i < 2; ++i) {
            int l = t + 256 * i;
            int kk = l >> 5, col = (l & 31) * 4;
            const float* src = (col < 64)
                ? &W0[(size_t)(k0 + kk) * 64 + col]
                : &W1[(size_t)(k0 + kk) * 64 + (col - 64)];
            float4 v = *(const float4*)src;
            float vv[4] = {v.x, v.y, v.z, v.w};
#pragma unroll
            for (int j = 0; j < 4; ++j) {
                float hi = tf32r(vv[j]);
                float lo = tf32r(vv[j] - hi);
                Wh[kk][col + j] = __float_as_uint(hi);
                Wl[kk][col + j] = __float_as_uint(lo);
            }
        }
        __syncthreads();

#pragma unroll
        for (int ks = 0; ks < KC / 8; ++ks) {
            const int kb = ks * 8;
            uint32_t ah[2][4], al[2][4];
#pragma unroll
            for (int mt = 0; mt < 2; ++mt) {
                int r = rbase + mt * 16 + g;
                ah[mt][0] = Ah[kb + c][r];     ah[mt][1] = Ah[kb + c][r + 8];
                ah[mt][2] = Ah[kb + c + 4][r]; ah[mt][3] = Ah[kb + c + 4][r + 8];
                al[mt][0] = Al[kb + c][r];     al[mt][1] = Al[kb + c][r + 8];
                al[mt][2] = Al[kb + c + 4][r]; al[mt][3] = Al[kb + c + 4][r + 8];
            }
#pragma unroll
            for (int nt = 0; nt < 8; ++nt) {
                int n = nbase0 + nt * 8 + g;
                uint32_t bh0 = Wh[kb + c][n],     bh1 = Wh[kb + c + 4][n];
                uint32_t bl0 = Wl[kb + c][n],     bl1 = Wl[kb + c + 4][n];
#pragma unroll
                for (int mt = 0; mt < 2; ++mt) {
                    MMA_TF32(d[mt][nt], ah[mt], bh0, bh1);
                    MMA_TF32(d[mt][nt], ah[mt], bl0, bl1);
                    MMA_TF32(d[mt][nt], al[mt], bh0, bh1);
                }
            }
        }
    }

    float* O = (wn == 0) ? O0 : O1;
#pragma unroll
    for (int mt = 0; mt < 2; ++mt) {
#pragma unroll
        for (int nt = 0; nt < 8; ++nt) {
            int nn = nt * 8 + 2 * c;
            int r0w = row0 + rbase + mt * 16 + g;
            if (r0w < M)
                *(float2*)&O[(size_t)r0w * 64 + nn] =
                    make_float2(d[mt][nt][0], d[mt][nt][1]);
            int r1w = r0w + 8;
            if (r1w < M)
                *(float2*)&O[(size_t)r1w * 64 + nn] =
                    make_float2(d[mt][nt][2], d[mt][nt][3]);
        }
    }
}

// ---------------- fused GATv2 edge pass (node-parallel softmax) -------------
// 4 lanes per dst node in NATURAL order (coalesced xr reads / agg writes —
// degree-sorting regressed in R8 by scattering these). Plain exp softmax:
// scores are bounded (|e| << 88) and the self-loop keeps s well-scaled, so
// the running-max rescale of online softmax is dropped; the softmax ratio is
// mathematically identical. 1-edge-deep src-row prefetch.
// Epilogue adds bias, writes agg, accumulates BN stats.
__global__ void gat_fused(const int* __restrict__ srcb,
                          const int* __restrict__ off,
                          const int* __restrict__ deg,
                          const float* __restrict__ xl,
                          const float* __restrict__ xr,
                          const float* __restrict__ att,
                          const float* __restrict__ bias,
                          float* __restrict__ agg,
                          float* __restrict__ st, int N) {
    __shared__ float ssum[64], ssq[64];
    const int t = threadIdx.x;
    int g = blockIdx.x * blockDim.x + t;
    int node = g >> 2;
    int lane = g & 3;
    bool valid = node < N;
    int nd = valid ? node : 0;

    const unsigned gmask = 0xFu << ((t & 31) & ~3);

    if (t < 64) { ssum[t] = 0.f; ssq[t] = 0.f; }

    const float4* xr4 = (const float4*)(xr + (size_t)nd * 64) + lane * 4;
    float4 r0 = xr4[0], r1 = xr4[1], r2 = xr4[2], r3 = xr4[3];
    const float4* at4 = (const float4*)att + lane * 4;
    float4 a0 = at4[0], a1 = at4[1], a2 = at4[2], a3 = at4[3];

    int base = valid ? off[nd] : 0;
    int cnt  = valid ? deg[nd] : 0;

    float s = 0.f;
    float4 c0 = make_float4(0.f,0.f,0.f,0.f), c1 = c0, c2 = c0, c3 = c0;
    float4 l0, l1, l2, l3;

    if (cnt > 0) {
        int src = __ldg(&srcb[base]);
        const float4* p = (const float4*)(xl + (size_t)src * 64) + lane * 4;
        l0 = p[0]; l1 = p[1]; l2 = p[2]; l3 = p[3];
    }

    for (int j = 0; j < cnt; ++j) {
        float4 n0, n1, n2, n3;
        bool more = (j + 1 < cnt);
        if (more) {
            int ns = __ldg(&srcb[base + j + 1]);
            const float4* p = (const float4*)(xl + (size_t)ns * 64) + lane * 4;
            n0 = p[0]; n1 = p[1]; n2 = p[2]; n3 = p[3];
        }

        float e = 0.f, v;
#define EQ(L, R, A) \
        v = L.x + R.x; e += A.x * fmaxf(v, 0.2f * v); \
        v = L.y + R.y; e += A.y * fmaxf(v, 0.2f * v); \
        v = L.z + R.z; e += A.z * fmaxf(v, 0.2f * v); \
        v = L.w + R.w; e += A.w * fmaxf(v, 0.2f * v);
        EQ(l0, r0, a0) EQ(l1, r1, a1) EQ(l2, r2, a2) EQ(l3, r3, a3)
#undef EQ
        e += __shfl_xor_sync(gmask, e, 1);
        e += __shfl_xor_sync(gmask, e, 2);

        float p = __expf(e);
        s += p;
#define AQ(C, L) \
        C.x += p * L.x; C.y += p * L.y; \
        C.z += p * L.z; C.w += p * L.w;
        AQ(c0, l0) AQ(c1, l1) AQ(c2, l2) AQ(c3, l3)
#undef AQ
        if (more) { l0 = n0; l1 = n1; l2 = n2; l3 = n3; }
    }

    float inv = 1.f / (s + 1e-16f);
    const float4* bq = (const float4*)bias + lane * 4;
    float4 b0 = bq[0], b1 = bq[1], b2 = bq[2], b3 = bq[3];
    float x[16];
#define XQ(q, C, B) \
    x[4*q+0] = C.x * inv + B.x; x[4*q+1] = C.y * inv + B.y; \
    x[4*q+2] = C.z * inv + B.z; x[4*q+3] = C.w * inv + B.w;
    XQ(0, c0, b0) XQ(1, c1, b1) XQ(2, c2, b2) XQ(3, c3, b3)
#undef XQ

    if (valid) {
        float4* o = (float4*)(agg + (size_t)node * 64) + lane * 4;
        o[0] = make_float4(x[0],  x[1],  x[2],  x[3]);
        o[1] = make_float4(x[4],  x[5],  x[6],  x[7]);
        o[2] = make_float4(x[8],  x[9],  x[10], x[11]);
        o[3] = make_float4(x[12], x[13], x[14], x[15]);
    }
    if (!valid) {
#pragma unroll
        for (int i = 0; i < 16; ++i) x[i] = 0.f;
    }

    __syncthreads();   // ssum/ssq zero-init visible
#pragma unroll
    for (int i = 0; i < 16; ++i) {
        float sv = x[i];
        float qv = x[i] * x[i];
        sv += __shfl_down_sync(0xffffffffu, sv, 16);
        sv += __shfl_down_sync(0xffffffffu, sv, 8);
        sv += __shfl_down_sync(0xffffffffu, sv, 4);
        qv += __shfl_down_sync(0xffffffffu, qv, 16);
        qv += __shfl_down_sync(0xffffffffu, qv, 8);
        qv += __shfl_down_sync(0xffffffffu, qv, 4);
        if ((t & 31) < 4) {
            int ch = lane * 16 + i;
            atomicAdd(&ssum[ch], sv);
            atomicAdd(&ssq[ch], qv);
        }
    }
    __syncthreads();
    if (t < 64) {
        atomicAdd(&st[t], ssum[t]);
        atomicAdd(&st[64 + t], ssq[t]);
    }
}

// ---------------- BN prep: st -> (scale, shift); zero st for next layer -----
__global__ void prep_bn(const float* __restrict__ st,
                        const float* __restrict__ gamma,
                        const float* __restrict__ beta,
                        float* __restrict__ bnp,
                        float* __restrict__ st_mut, int N) {
    int t = threadIdx.x;   // 128 threads, 1 block
    float scale = 0.f, shift = 0.f;
    if (t < 64) {
        float invN = 1.f / (float)N;
        float mu  = st[t] * invN;
        float var = st[64 + t] * invN - mu * mu;
        float rs  = rsqrtf(var + 1e-5f);
        scale = gamma[t] * rs;
        shift = beta[t] - mu * scale;
    }
    __syncthreads();       // reads done before zeroing
    if (t < 64) { bnp[t] = scale; bnp[64 + t] = shift; }
    st_mut[t] = 0.f;
}

// ---------------- final head: BN(no affine) on [:,:32], softplus [:,32:] ----
__global__ void final_k(const float* __restrict__ v,
                        const float* __restrict__ st,
                        float* __restrict__ out, int N) {
    int i = blockIdx.x * blockDim.x + threadIdx.x;
    if (i >= N * 64) return;
    int n = i >> 6, c = i & 63;
    float x = v[i];
    if (c < 32) {
        float invN = 1.f / (float)N;
        float mu = st[c] * invN;
        float var = st[64 + c] * invN - mu * mu;
        out[(size_t)n * 32 + c] = (x - mu) * rsqrtf(var + 1e-5f);
    } else {
        float sp = fmaxf(x, 0.f) + log1pf(expf(-fabsf(x)));
        out[(size_t)N * 32 + (size_t)n * 32 + (c - 32)] = sp;
    }
}

// ---------------- host launcher ---------------------------------------------
extern "C" void kernel_launch(void* const* d_in, const int* in_sizes, int n_in,
                              void* d_out, int out_size) {
    const float* x    = (const float*)d_in[0];
    const void*  ei   = d_in[1];
    const float* Wl1  = (const float*)d_in[2];
    const float* Wr1  = (const float*)d_in[3];
    const float* att1 = (const float*)d_in[4];
    const float* b1   = (const float*)d_in[5];
    const float* ga1  = (const float*)d_in[6];
    const float* be1  = (const float*)d_in[7];
    const float* Wl2  = (const float*)d_in[8];
    const float* Wr2  = (const float*)d_in[9];
    const float* att2 = (const float*)d_in[10];
    const float* b2   = (const float*)d_in[11];
    float* out = (float*)d_out;

    const int N  = in_sizes[0] / 128;   // 50000
    const int E  = in_sizes[1] / 2;     // 800000
    const int EE = E + N;               // + self loops

    float *p_xl, *p_xr, *p_agg, *p_st, *p_bnp;
    int *p_srcb, *p_off, *p_deg, *p_cur, *p_bsum, *p_bofs;
    cudaGetSymbolAddress((void**)&p_xl,   g_xl);
    cudaGetSymbolAddress((void**)&p_xr,   g_xr);
    cudaGetSymbolAddress((void**)&p_agg,  g_agg);
    cudaGetSymbolAddress((void**)&p_st,   g_st);
    cudaGetSymbolAddress((void**)&p_bnp,  g_bnp);
    cudaGetSymbolAddress((void**)&p_srcb, g_srcb);
    cudaGetSymbolAddress((void**)&p_off,  g_off);
    cudaGetSymbolAddress((void**)&p_deg,  g_deg);
    cudaGetSymbolAddress((void**)&p_cur,  g_cur);
    cudaGetSymbolAddress((void**)&p_bsum, g_bsum);
    cudaGetSymbolAddress((void**)&p_bofs, g_bofs);

    const int TB = 256;
    const int gEdge  = (EE + TB - 1) / TB;
    const int gGemm  = (N + 127) / 128;
    const int gFuse  = (N * 4 + TB - 1) / TB;
    const int gElem  = (N * 64 + TB - 1) / TB;
    const int gScan  = (N + 1023) / 1024;     // 49 blocks

    // ---- CSR build (shared by both layers) ----
    detect_k<<<1, 32>>>((const int*)ei, E);
    cudaMemsetAsync(p_deg, 0, (size_t)N * sizeof(int));
    hist_k<<<gEdge, TB>>>(ei, p_deg, E, EE);
    blocksum_k<<<gScan, TB>>>(p_deg, p_bsum, N);
    topscan_k<<<1, 128>>>(p_bsum, p_bofs, p_st, gScan);
    fill_k<<<gScan, TB>>>(p_deg, p_bofs, p_off, p_cur, N);
    scatter_k<<<gEdge, TB>>>(ei, p_cur, p_srcb, E, EE);

    // ---- layer 1 ----
    gemm_tf32<<<gGemm, TB>>>(x, Wl1, Wr1, nullptr, p_xl, p_xr, N, 128);
    gat_fused<<<gFuse, TB>>>(p_srcb, p_off, p_deg, p_xl, p_xr, att1, b1,
                             p_agg, p_st, N);
    prep_bn<<<1, 128>>>(p_st, ga1, be1, p_bnp, p_st, N);

    // ---- layer 2 (BN+ReLU fused into gemm A-staging) ----
    gemm_tf32<<<gGemm, TB>>>(p_agg, Wl2, Wr2, p_bnp, p_xl, p_xr, N, 64);
    gat_fused<<<gFuse, TB>>>(p_srcb, p_off, p_deg, p_xl, p_xr, att2, b2,
                             p_agg, p_st, N);
    final_k<<<gElem, TB>>>(p_agg, p_st, out, N);
}

// round 10
// speedup vs baseline: 1.2159x; 1.0375x over previous
#include <cuda_runtime.h>
#include <math.h>
#include <stdint.h>

// Problem constants (shapes fixed by the dataset)
#define NNODES 50000
#define NEDGES 800000
#define EETOT  (NNODES + NEDGES)
#define C64    64

typedef unsigned long long u64;

// ---------------- scratch (static device globals; no allocation allowed) ---
__device__ __align__(256) float g_xl [NNODES * C64];
__device__ __align__(256) float g_xr [NNODES * C64];
__device__ __align__(256) float g_agg[NNODES * C64];
__device__ __align__(256) int   g_srcb[EETOT];      // CSR src ids (sorted by dst)
__device__ __align__(256) int   g_off [NNODES];     // CSR row offsets
__device__ __align__(256) int   g_deg [NNODES];     // in-degree per node (incl self)
__device__ __align__(256) int   g_cur [NNODES];     // scatter cursors
__device__ __align__(256) int   g_bsum[64];         // per-block degree sums
__device__ __align__(256) int   g_bofs[64];         // exclusive scan of bsum
__device__ __align__(256) float g_st [128];         // per-channel sum / sumsq
__device__ __align__(256) float g_bnp[128];         // BN scale / shift
__device__ int g_idx64;                              // 1 if edge_index is int64

// ---------------- helpers ---------------------------------------------------
__device__ __forceinline__ float tf32r(float x) {
    uint32_t u;
    asm("cvt.rna.tf32.f32 %0, %1;" : "=r"(u) : "f"(x));
    return __uint_as_float(u);
}

__device__ __forceinline__ u64 fx_add(u64 a, u64 b) {
    u64 r; asm("add.rn.f32x2 %0,%1,%2;" : "=l"(r) : "l"(a), "l"(b)); return r;
}
__device__ __forceinline__ u64 fx_fma(u64 a, u64 b, u64 c) {
    u64 r; asm("fma.rn.f32x2 %0,%1,%2,%3;" : "=l"(r) : "l"(a), "l"(b), "l"(c)); return r;
}
__device__ __forceinline__ u64 fx_pack(float x, float y) {
    u64 r; asm("mov.b64 %0,{%1,%2};" : "=l"(r) : "f"(x), "f"(y)); return r;
}
__device__ __forceinline__ float2 fx_unpack(u64 a) {
    float x, y; asm("mov.b64 {%0,%1},%2;" : "=f"(x), "=f"(y) : "l"(a));
    return make_float2(x, y);
}

#define MMA_TF32(d, a, b0, b1) \
    asm volatile("mma.sync.aligned.m16n8k8.row.col.f32.tf32.tf32.f32 " \
                 "{%0,%1,%2,%3}, {%4,%5,%6,%7}, {%8,%9}, {%0,%1,%2,%3};" \
                 : "+f"((d)[0]), "+f"((d)[1]), "+f"((d)[2]), "+f"((d)[3]) \
                 : "r"((a)[0]), "r"((a)[1]), "r"((a)[2]), "r"((a)[3]), \
                   "r"(b0), "r"(b1))

// zero deg to 1 (self-loop pre-counted); block 0 warp 0 detects int64 vs int32
__global__ void zero_detect_k(const int* ei32, int E, int* __restrict__ deg,
                              int N) {
    int i = blockIdx.x * blockDim.x + threadIdx.x;
    if (i < N) deg[i] = 1;
    if (blockIdx.x == 0 && threadIdx.x < 32) {
        int t = threadIdx.x;
        int nz = 0;
        if (2 * t + 1 < 2 * E)        nz |= (ei32[2 * t + 1] != 0);
        if (2 * (t + 32) + 1 < 2 * E) nz |= (ei32[2 * (t + 32) + 1] != 0);
        nz = __any_sync(0xffffffffu, nz);
        if (t == 0) g_idx64 = nz ? 0 : 1;
    }
}

// ---------------- CSR build -------------------------------------------------
// histogram over REAL edges only (self-loops pre-counted), 2 edges/thread
__global__ void hist_k(const void* __restrict__ ei, int* __restrict__ deg,
                       int E) {
    int i = blockIdx.x * blockDim.x + threadIdx.x;
    int e0 = 2 * i;
    if (e0 >= E) return;
    int d0, d1 = -1;
    bool pair = ((E & 1) == 0) && (e0 + 1 < E);
    if (g_idx64) {
        const long long* p = (const long long*)ei + E;
        if (pair) { longlong2 v = *(const longlong2*)(p + e0);
                    d0 = (int)v.x; d1 = (int)v.y; }
        else { d0 = (int)p[e0]; if (e0 + 1 < E) d1 = (int)p[e0 + 1]; }
    } else {
        const int* p = (const int*)ei + E;
        if (pair) { int2 v = *(const int2*)(p + e0); d0 = v.x; d1 = v.y; }
        else { d0 = p[e0]; if (e0 + 1 < E) d1 = p[e0 + 1]; }
    }
    atomicAdd(&deg[d0], 1);
    if (d1 >= 0) atomicAdd(&deg[d1], 1);
}

// per-block (1024 nodes) degree sums
__global__ void blocksum_k(const int* __restrict__ deg, int* __restrict__ bsum,
                           int N) {
    __shared__ int ws[8];
    int t = threadIdx.x;                 // 256
    int i0 = blockIdx.x * 1024 + t * 4;
    int s = 0;
    if (i0 + 3 < N) {
        int4 v = *(const int4*)&deg[i0];
        s = v.x + v.y + v.z + v.w;
    } else {
        for (int j = 0; j < 4; ++j) if (i0 + j < N) s += deg[i0 + j];
    }
#pragma unroll
    for (int o = 16; o; o >>= 1) s += __shfl_down_sync(0xffffffffu, s, o);
    if ((t & 31) == 0) ws[t >> 5] = s;
    __syncthreads();
    if (t == 0) {
        int tot = 0;
#pragma unroll
        for (int i = 0; i < 8; ++i) tot += ws[i];
        bsum[blockIdx.x] = tot;
    }
}

// exclusive scan of ≤64 block sums; also zero BN stats for layer 1
__global__ void topscan_k(const int* __restrict__ bsum, int* __restrict__ bofs,
                          float* __restrict__ st, int nb) {
    int t = threadIdx.x;                 // 128
    st[t] = 0.f;
    __shared__ int sh[64];
    if (t < 64) {
        int lane = t & 31;
        int v = (t < nb) ? bsum[t] : 0;
        int inc = v;
#pragma unroll
        for (int o = 1; o < 32; o <<= 1) {
            int u = __shfl_up_sync(0xffffffffu, inc, o);
            if (lane >= o) inc += u;
        }
        sh[t] = inc;
    }
    __syncthreads();
    if (t < 64) {
        int add = (t >= 32) ? sh[31] : 0;
        int inc = sh[t] + add;
        int v = (t < nb) ? bsum[t] : 0;
        bofs[t] = inc - v;
    }
}

// per-block fill of off/cur via hierarchical scan; inserts self-loop at the
// head of each node's bucket and starts cur past it.
__global__ void fill_k(const int* __restrict__ deg, const int* __restrict__ bofs,
                       int* __restrict__ off, int* __restrict__ cur,
                       int* __restrict__ srcb, int N) {
    __shared__ int wsum[8];
    int t = threadIdx.x, lane = t & 31, warp = t >> 5;
    int i0 = blockIdx.x * 1024 + t * 4;
    int d0 = 0, d1 = 0, d2 = 0, d3 = 0;
    if (i0 + 3 < N) {
        int4 v = *(const int4*)&deg[i0];
        d0 = v.x; d1 = v.y; d2 = v.z; d3 = v.w;
    } else {
        if (i0     < N) d0 = deg[i0];
        if (i0 + 1 < N) d1 = deg[i0 + 1];
        if (i0 + 2 < N) d2 = deg[i0 + 2];
    }
    int tsum = d0 + d1 + d2 + d3;
    int inc = tsum;
#pragma unroll
    for (int o = 1; o < 32; o <<= 1) {
        int u = __shfl_up_sync(0xffffffffu, inc, o);
        if (lane >= o) inc += u;
    }
    if (lane == 31) wsum[warp] = inc;
    __syncthreads();
    int wofs = 0;
#pragma unroll
    for (int wi = 0; wi < 8; ++wi) if (wi < warp) wofs += wsum[wi];
    int base = bofs[blockIdx.x] + wofs + inc - tsum;
    int o0 = base, o1 = o0 + d0, o2 = o1 + d1, o3 = o2 + d2;
    if (i0 + 3 < N) {
        *(int4*)&off[i0] = make_int4(o0, o1, o2, o3);
        *(int4*)&cur[i0] = make_int4(o0 + 1, o1 + 1, o2 + 1, o3 + 1);
        srcb[o0] = i0;     srcb[o1] = i0 + 1;
        srcb[o2] = i0 + 2; srcb[o3] = i0 + 3;
    } else {
        if (i0     < N) { off[i0]     = o0; cur[i0]     = o0 + 1; srcb[o0] = i0; }
        if (i0 + 1 < N) { off[i0 + 1] = o1; cur[i0 + 1] = o1 + 1; srcb[o1] = i0 + 1; }
        if (i0 + 2 < N) { off[i0 + 2] = o2; cur[i0 + 2] = o2 + 1; srcb[o2] = i0 + 2; }
    }
}

// scatter REAL edges, 2 per thread
__global__ void scatter_k(const void* __restrict__ ei, int* __restrict__ cur,
                          int* __restrict__ srcb, int E) {
    int i = blockIdx.x * blockDim.x + threadIdx.x;
    int e0 = 2 * i;
    if (e0 >= E) return;
    int s0, s1 = -1, d0, d1 = -1;
    bool pair = ((E & 1) == 0) && (e0 + 1 < E);
    if (g_idx64) {
        const long long* ps = (const long long*)ei;
        const long long* pd = ps + E;
        if (pair) {
            longlong2 vs = *(const longlong2*)(ps + e0);
            longlong2 vd = *(const longlong2*)(pd + e0);
            s0 = (int)vs.x; s1 = (int)vs.y; d0 = (int)vd.x; d1 = (int)vd.y;
        } else {
            s0 = (int)ps[e0]; d0 = (int)pd[e0];
            if (e0 + 1 < E) { s1 = (int)ps[e0 + 1]; d1 = (int)pd[e0 + 1]; }
        }
    } else {
        const int* ps = (const int*)ei;
        const int* pd = ps + E;
        if (pair) {
            int2 vs = *(const int2*)(ps + e0);
            int2 vd = *(const int2*)(pd + e0);
            s0 = vs.x; s1 = vs.y; d0 = vd.x; d1 = vd.y;
        } else {
            s0 = ps[e0]; d0 = pd[e0];
            if (e0 + 1 < E) { s1 = ps[e0 + 1]; d1 = pd[e0 + 1]; }
        }
    }
    int pos = atomicAdd(&cur[d0], 1);
    srcb[pos] = s0;
    if (d1 >= 0) {
        int pos1 = atomicAdd(&cur[d1], 1);
        srcb[pos1] = s1;
    }
}

// ---------------- dual GEMM via tf32x3 tensor cores -------------------------
#define KC 16
__global__ void __launch_bounds__(256)
gemm_tf32(const float* __restrict__ A,
          const float* __restrict__ W0,
          const float* __restrict__ W1,
          const float* __restrict__ bnp,   // null = no BN
          float* __restrict__ O0, float* __restrict__ O1,
          int M, int K) {
    __shared__ uint32_t Ah[KC][136], Al[KC][136];
    __shared__ uint32_t Wh[KC][136], Wl[KC][136];
    const int t = threadIdx.x;
    const int lane = t & 31, warp = t >> 5;
    const int wm = warp >> 1, wn = warp & 1;
    const int g = lane >> 2, c = lane & 3;
    const int row0 = blockIdx.x * 128;
    const int rbase = wm * 32;
    const int nbase0 = wn * 64;

    float d[2][8][4];
#pragma unroll
    for (int i = 0; i < 2; ++i)
#pragma unroll
        for (int j = 0; j < 8; ++j)
#pragma unroll
            for (int q = 0; q < 4; ++q) d[i][j][q] = 0.f;

    const int nchunk = K / KC;
    for (int ch = 0; ch < nchunk; ++ch) {
        const int k0 = ch * KC;
        __syncthreads();
#pragma unroll
        for (int i = 0; i < 2; ++i) {
            int l = t + 256 * i;
            int r = l >> 2, kq = (l & 3) * 4;
            float4 v = make_float4(0.f, 0.f, 0.f, 0.f);
            if (row0 + r < M)
                v = *(const float4*)&A[(size_t)(row0 + r) * K + k0 + kq];
            if (bnp) {
                float4 sc = *(const float4*)&bnp[k0 + kq];
                float4 sh = *(const float4*)&bnp[64 + k0 + kq];
                v.x = fmaxf(v.x * sc.x + sh.x, 0.f);
                v.y = fmaxf(v.y * sc.y + sh.y, 0.f);
                v.z = fmaxf(v.z * sc.z + sh.z, 0.f);
                v.w = fmaxf(v.w * sc.w + sh.w, 0.f);
            }
            float vv[4] = {v.x, v.y, v.z, v.w};
#pragma unroll
            for (int j = 0; j < 4; ++j) {
                float hi = tf32r(vv[j]);
                float lo = tf32r(vv[j] - hi);
                Ah[kq + j][r] = __float_as_uint(hi);
                Al[kq + j][r] = __float_as_uint(lo);
            }
        }
#pragma unroll
        for (int i = 0; i < 2; ++i) {
            int l = t + 256 * i;
            int kk = l >> 5, col = (l & 31) * 4;
            const float* src = (col < 64)
                ? &W0[(size_t)(k0 + kk) * 64 + col]
                : &W1[(size_t)(k0 + kk) * 64 + (col - 64)];
            float4 v = *(const float4*)src;
            float vv[4] = {v.x, v.y, v.z, v.w};
#pragma unroll
            for (int j = 0; j < 4; ++j) {
                float hi = tf32r(vv[j]);
                float lo = tf32r(vv[j] - hi);
                Wh[kk][col + j] = __float_as_uint(hi);
                Wl[kk][col + j] = __float_as_uint(lo);
            }
        }
        __syncthreads();

#pragma unroll
        for (int ks = 0; ks < KC / 8; ++ks) {
            const int kb = ks * 8;
            uint32_t ah[2][4], al[2][4];
#pragma unroll
            for (int mt = 0; mt < 2; ++mt) {
                int r = rbase + mt * 16 + g;
                ah[mt][0] = Ah[kb + c][r];     ah[mt][1] = Ah[kb + c][r + 8];
                ah[mt][2] = Ah[kb + c + 4][r]; ah[mt][3] = Ah[kb + c + 4][r + 8];
                al[mt][0] = Al[kb + c][r];     al[mt][1] = Al[kb + c][r + 8];
                al[mt][2] = Al[kb + c + 4][r]; al[mt][3] = Al[kb + c + 4][r + 8];
            }
#pragma unroll
            for (int nt = 0; nt < 8; ++nt) {
                int n = nbase0 + nt * 8 + g;
                uint32_t bh0 = Wh[kb + c][n],     bh1 = Wh[kb + c + 4][n];
                uint32_t bl0 = Wl[kb + c][n],     bl1 = Wl[kb + c + 4][n];
#pragma unroll
                for (int mt = 0; mt < 2; ++mt) {
                    MMA_TF32(d[mt][nt], ah[mt], bh0, bh1);
                    MMA_TF32(d[mt][nt], ah[mt], bl0, bl1);
                    MMA_TF32(d[mt][nt], al[mt], bh0, bh1);
                }
            }
        }
    }

    float* O = (wn == 0) ? O0 : O1;
#pragma unroll
    for (int mt = 0; mt < 2; ++mt) {
#pragma unroll
        for (int nt = 0; nt < 8; ++nt) {
            int nn = nt * 8 + 2 * c;
            int r0w = row0 + rbase + mt * 16 + g;
            if (r0w < M)
                *(float2*)&O[(size_t)r0w * 64 + nn] =
                    make_float2(d[mt][nt][0], d[mt][nt][1]);
            int r1w = r0w + 8;
            if (r1w < M)
                *(float2*)&O[(size_t)r1w * 64 + nn] =
                    make_float2(d[mt][nt][2], d[mt][nt][3]);
        }
    }
}

// ---------------- fused GATv2 edge pass (node-parallel softmax, f32x2) ------
// 4 lanes per dst node in natural order (coalesced xr/agg). Packed f32x2
// math: leakyrelu(v) = 0.6v + 0.4|v|, so e-contrib = (0.6a)v + (0.4a)|v|
// with pre-scaled att vectors. Plain exp softmax (scores bounded; self-loop
// keeps s well-scaled). A/B double-buffered prefetch, no register copies.
// Epilogue adds bias, writes agg, accumulates BN stats.
__global__ void gat_fused(const int* __restrict__ srcb,
                          const int* __restrict__ off,
                          const int* __restrict__ deg,
                          const float* __restrict__ xl,
                          const float* __restrict__ xr,
                          const float* __restrict__ att,
                          const float* __restrict__ bias,
                          float* __restrict__ agg,
                          float* __restrict__ st, int N) {
    __shared__ float ssum[64], ssq[64];
    const int t = threadIdx.x;
    int g = blockIdx.x * blockDim.x + t;
    int node = g >> 2;
    int lane = g & 3;
    bool valid = node < N;
    int nd = valid ? node : 0;

    const unsigned gmask = 0xFu << ((t & 31) & ~3);

    if (t < 64) { ssum[t] = 0.f; ssq[t] = 0.f; }

    // xr row (16 channels = 8 packed pairs)
    u64 rr[8];
    {
        const ulonglong2* p = (const ulonglong2*)(xr + (size_t)nd * 64) + lane * 4;
        ulonglong2 q0 = p[0], q1 = p[1], q2 = p[2], q3 = p[3];
        rr[0] = q0.x; rr[1] = q0.y; rr[2] = q1.x; rr[3] = q1.y;
        rr[4] = q2.x; rr[5] = q2.y; rr[6] = q3.x; rr[7] = q3.y;
    }
    // pre-scaled attention pairs
    u64 a06[8], a04[8];
    {
        const float* ap = att + lane * 16;
#pragma unroll
        for (int i = 0; i < 8; ++i) {
            float u = ap[2 * i], w = ap[2 * i + 1];
            a06[i] = fx_pack(0.6f * u, 0.6f * w);
            a04[i] = fx_pack(0.4f * u, 0.4f * w);
        }
    }

    int base = valid ? off[nd] : 0;
    int cnt  = valid ? deg[nd] : 0;

    float s = 0.f;
    u64 cc[8] = {0, 0, 0, 0, 0, 0, 0, 0};
    u64 A[8], B[8];

#define LOADE(BUF, IDX) do { \
        int _s = __ldg(&srcb[base + (IDX)]); \
        const ulonglong2* _p = (const ulonglong2*)(xl + (size_t)_s * 64) + lane * 4; \
        ulonglong2 _q0 = _p[0], _q1 = _p[1], _q2 = _p[2], _q3 = _p[3]; \
        BUF[0] = _q0.x; BUF[1] = _q0.y; BUF[2] = _q1.x; BUF[3] = _q1.y; \
        BUF[4] = _q2.x; BUF[5] = _q2.y; BUF[6] = _q3.x; BUF[7] = _q3.y; } while(0)

#define PROC(BUF) do { \
        u64 e2 = 0; \
        _Pragma("unroll") \
        for (int _q = 0; _q < 8; ++_q) { \
            u64 v2 = fx_add(BUF[_q], rr[_q]); \
            e2 = fx_fma(a06[_q], v2, e2); \
            e2 = fx_fma(a04[_q], v2 & 0x7FFFFFFF7FFFFFFFULL, e2); \
        } \
        float2 eh = fx_unpack(e2); \
        float e = eh.x + eh.y; \
        e += __shfl_xor_sync(gmask, e, 1); \
        e += __shfl_xor_sync(gmask, e, 2); \
        float pv = __expf(e); \
        s += pv; \
        u64 pp = fx_pack(pv, pv); \
        _Pragma("unroll") \
        for (int _q = 0; _q < 8; ++_q) cc[_q] = fx_fma(pp, BUF[_q], cc[_q]); } while(0)

    if (cnt > 0) LOADE(A, 0);
    int j = 0;
    for (; j + 2 <= cnt; j += 2) {
        LOADE(B, j + 1);
        PROC(A);
        if (j + 2 < cnt) LOADE(A, j + 2);
        PROC(B);
    }
    if (j < cnt) PROC(A);
#undef LOADE
#undef PROC

    float inv = 1.f / (s + 1e-16f);
    const float* bp = bias + lane * 16;
    float x[16];
#pragma unroll
    for (int q = 0; q < 8; ++q) {
        float2 cv = fx_unpack(cc[q]);
        x[2 * q]     = cv.x * inv + bp[2 * q];
        x[2 * q + 1] = cv.y * inv + bp[2 * q + 1];
    }

    if (valid) {
        float4* o = (float4*)(agg + (size_t)node * 64) + lane * 4;
        o[0] = make_float4(x[0],  x[1],  x[2],  x[3]);
        o[1] = make_float4(x[4],  x[5],  x[6],  x[7]);
        o[2] = make_float4(x[8],  x[9],  x[10], x[11]);
        o[3] = make_float4(x[12], x[13], x[14], x[15]);
    }
    if (!valid) {
#pragma unroll
        for (int i = 0; i < 16; ++i) x[i] = 0.f;
    }

    __syncthreads();   // ssum/ssq zero-init visible
#pragma unroll
    for (int i = 0; i < 16; ++i) {
        float sv = x[i];
        float qv = x[i] * x[i];
        sv += __shfl_down_sync(0xffffffffu, sv, 16);
        sv += __shfl_down_sync(0xffffffffu, sv, 8);
        sv += __shfl_down_sync(0xffffffffu, sv, 4);
        qv += __shfl_down_sync(0xffffffffu, qv, 16);
        qv += __shfl_down_sync(0xffffffffu, qv, 8);
        qv += __shfl_down_sync(0xffffffffu, qv, 4);
        if ((t & 31) < 4) {
            int ch = lane * 16 + i;
            atomicAdd(&ssum[ch], sv);
            atomicAdd(&ssq[ch], qv);
        }
    }
    __syncthreads();
    if (t < 64) {
        atomicAdd(&st[t], ssum[t]);
        atomicAdd(&st[64 + t], ssq[t]);
    }
}

// ---------------- BN prep: st -> (scale, shift); zero st for next layer -----
__global__ void prep_bn(const float* __restrict__ st,
                        const float* __restrict__ gamma,
                        const float* __restrict__ beta,
                        float* __restrict__ bnp,
                        float* __restrict__ st_mut, int N) {
    int t = threadIdx.x;   // 128 threads, 1 block
    float scale = 0.f, shift = 0.f;
    if (t < 64) {
        float invN = 1.f / (float)N;
        float mu  = st[t] * invN;
        float var = st[64 + t] * invN - mu * mu;
        float rs  = rsqrtf(var + 1e-5f);
        scale = gamma[t] * rs;
        shift = beta[t] - mu * scale;
    }
    __syncthreads();       // reads done before zeroing
    if (t < 64) { bnp[t] = scale; bnp[64 + t] = shift; }
    st_mut[t] = 0.f;
}

// ---------------- final head: BN(no affine) on [:,:32], softplus [:,32:] ----
__global__ void final_k(const float* __restrict__ v,
                        const float* __restrict__ st,
                        float* __restrict__ out, int N) {
    int i = blockIdx.x * blockDim.x + threadIdx.x;
    if (i >= N * 64) return;
    int n = i >> 6, c = i & 63;
    float x = v[i];
    if (c < 32) {
        float invN = 1.f / (float)N;
        float mu = st[c] * invN;
        float var = st[64 + c] * invN - mu * mu;
        out[(size_t)n * 32 + c] = (x - mu) * rsqrtf(var + 1e-5f);
    } else {
        float sp = fmaxf(x, 0.f) + log1pf(expf(-fabsf(x)));
        out[(size_t)N * 32 + (size_t)n * 32 + (c - 32)] = sp;
    }
}

// ---------------- host launcher ---------------------------------------------
extern "C" void kernel_launch(void* const* d_in, const int* in_sizes, int n_in,
                              void* d_out, int out_size) {
    const float* x    = (const float*)d_in[0];
    const void*  ei   = d_in[1];
    const float* Wl1  = (const float*)d_in[2];
    const float* Wr1  = (const float*)d_in[3];
    const float* att1 = (const float*)d_in[4];
    const float* b1   = (const float*)d_in[5];
    const float* ga1  = (const float*)d_in[6];
    const float* be1  = (const float*)d_in[7];
    const float* Wl2  = (const float*)d_in[8];
    const float* Wr2  = (const float*)d_in[9];
    const float* att2 = (const float*)d_in[10];
    const float* b2   = (const float*)d_in[11];
    float* out = (float*)d_out;

    const int N  = in_sizes[0] / 128;   // 50000
    const int E  = in_sizes[1] / 2;     // 800000

    float *p_xl, *p_xr, *p_agg, *p_st, *p_bnp;
    int *p_srcb, *p_off, *p_deg, *p_cur, *p_bsum, *p_bofs;
    cudaGetSymbolAddress((void**)&p_xl,   g_xl);
    cudaGetSymbolAddress((void**)&p_xr,   g_xr);
    cudaGetSymbolAddress((void**)&p_agg,  g_agg);
    cudaGetSymbolAddress((void**)&p_st,   g_st);
    cudaGetSymbolAddress((void**)&p_bnp,  g_bnp);
    cudaGetSymbolAddress((void**)&p_srcb, g_srcb);
    cudaGetSymbolAddress((void**)&p_off,  g_off);
    cudaGetSymbolAddress((void**)&p_deg,  g_deg);
    cudaGetSymbolAddress((void**)&p_cur,  g_cur);
    cudaGetSymbolAddress((void**)&p_bsum, g_bsum);
    cudaGetSymbolAddress((void**)&p_bofs, g_bofs);

    const int TB = 256;
    const int gEdge2 = ((E + 1) / 2 + TB - 1) / TB;   // 2 edges/thread
    const int gNode  = (N + TB - 1) / TB;
    const int gGemm  = (N + 127) / 128;
    const int gFuse  = (N * 4 + TB - 1) / TB;
    const int gElem  = (N * 64 + TB - 1) / TB;
    const int gScan  = (N + 1023) / 1024;     // 49 blocks

    // ---- CSR build (shared by both layers) ----
    zero_detect_k<<<gNode, TB>>>((const int*)ei, E, p_deg, N);
    hist_k<<<gEdge2, TB>>>(ei, p_deg, E);
    blocksum_k<<<gScan, TB>>>(p_deg, p_bsum, N);
    topscan_k<<<1, 128>>>(p_bsum, p_bofs, p_st, gScan);
    fill_k<<<gScan, TB>>>(p_deg, p_bofs, p_off, p_cur, p_srcb, N);
    scatter_k<<<gEdge2, TB>>>(ei, p_cur, p_srcb, E);

    // ---- layer 1 ----
    gemm_tf32<<<gGemm, TB>>>(x, Wl1, Wr1, nullptr, p_xl, p_xr, N, 128);
    gat_fused<<<gFuse, TB>>>(p_srcb, p_off, p_deg, p_xl, p_xr, att1, b1,
                             p_agg, p_st, N);
    prep_bn<<<1, 128>>>(p_st, ga1, be1, p_bnp, p_st, N);

    // ---- layer 2 (BN+ReLU fused into gemm A-staging) ----
    gemm_tf32<<<gGemm, TB>>>(p_agg, Wl2, Wr2, p_bnp, p_xl, p_xr, N, 64);
    gat_fused<<<gFuse, TB>>>(p_srcb, p_off, p_deg, p_xl, p_xr, att2, b2,
                             p_agg, p_st, N);
    final_k<<<gElem, TB>>>(p_agg, p_st, out, N);
}

// round 11
// speedup vs baseline: 1.2832x; 1.0553x over previous
#include <cuda_runtime.h>
#include <math.h>
#include <stdint.h>

// Problem constants (shapes fixed by the dataset)
#define NNODES 50000
#define NEDGES 800000
#define EETOT  (NNODES + NEDGES)
#define C64    64

typedef unsigned long long u64;

// ---------------- scratch (static device globals; no allocation allowed) ---
__device__ __align__(256) float g_xl [NNODES * C64];
__device__ __align__(256) float g_xr [NNODES * C64];
__device__ __align__(256) float g_agg[NNODES * C64];
__device__ __align__(256) int   g_srcb[EETOT];      // CSR src ids (sorted by dst)
__device__ __align__(256) int   g_off [NNODES];     // CSR row offsets
__device__ __align__(256) int   g_deg [NNODES];     // in-degree per node (incl self)
__device__ __align__(256) int   g_cur [NNODES];     // scatter cursors
__device__ __align__(256) int   g_bsum[64];         // per-block degree sums
__device__ __align__(256) int   g_bofs[64];         // exclusive scan of bsum
__device__ __align__(256) float g_st [128];         // per-channel sum / sumsq
__device__ __align__(256) float g_bnp[128];         // BN scale / shift
__device__ int g_idx64;                              // 1 if edge_index is int64

// ---------------- helpers ---------------------------------------------------
__device__ __forceinline__ float tf32r(float x) {
    uint32_t u;
    asm("cvt.rna.tf32.f32 %0, %1;" : "=r"(u) : "f"(x));
    return __uint_as_float(u);
}

__device__ __forceinline__ u64 fx_add(u64 a, u64 b) {
    u64 r; asm("add.rn.f32x2 %0,%1,%2;" : "=l"(r) : "l"(a), "l"(b)); return r;
}
__device__ __forceinline__ u64 fx_fma(u64 a, u64 b, u64 c) {
    u64 r; asm("fma.rn.f32x2 %0,%1,%2,%3;" : "=l"(r) : "l"(a), "l"(b), "l"(c)); return r;
}
__device__ __forceinline__ u64 fx_pack(float x, float y) {
    u64 r; asm("mov.b64 %0,{%1,%2};" : "=l"(r) : "f"(x), "f"(y)); return r;
}
__device__ __forceinline__ float2 fx_unpack(u64 a) {
    float x, y; asm("mov.b64 {%0,%1},%2;" : "=f"(x), "=f"(y) : "l"(a));
    return make_float2(x, y);
}

#define MMA_TF32(d, a, b0, b1) \
    asm volatile("mma.sync.aligned.m16n8k8.row.col.f32.tf32.tf32.f32 " \
                 "{%0,%1,%2,%3}, {%4,%5,%6,%7}, {%8,%9}, {%0,%1,%2,%3};" \
                 : "+f"((d)[0]), "+f"((d)[1]), "+f"((d)[2]), "+f"((d)[3]) \
                 : "r"((a)[0]), "r"((a)[1]), "r"((a)[2]), "r"((a)[3]), \
                   "r"(b0), "r"(b1))

// zero deg to 1 (self-loop pre-counted); block 0 warp 0 detects int64 vs int32
__global__ void zero_detect_k(const int* ei32, int E, int* __restrict__ deg,
                              int N) {
    int i = blockIdx.x * blockDim.x + threadIdx.x;
    if (i < N) deg[i] = 1;
    if (blockIdx.x == 0 && threadIdx.x < 32) {
        int t = threadIdx.x;
        int nz = 0;
        if (2 * t + 1 < 2 * E)        nz |= (ei32[2 * t + 1] != 0);
        if (2 * (t + 32) + 1 < 2 * E) nz |= (ei32[2 * (t + 32) + 1] != 0);
        nz = __any_sync(0xffffffffu, nz);
        if (t == 0) g_idx64 = nz ? 0 : 1;
    }
}

// ---------------- CSR build -------------------------------------------------
// histogram over REAL edges only (self-loops pre-counted), 2 edges/thread
__global__ void hist_k(const void* __restrict__ ei, int* __restrict__ deg,
                       int E) {
    int i = blockIdx.x * blockDim.x + threadIdx.x;
    int e0 = 2 * i;
    if (e0 >= E) return;
    int d0, d1 = -1;
    bool pair = ((E & 1) == 0) && (e0 + 1 < E);
    if (g_idx64) {
        const long long* p = (const long long*)ei + E;
        if (pair) { longlong2 v = *(const longlong2*)(p + e0);
                    d0 = (int)v.x; d1 = (int)v.y; }
        else { d0 = (int)p[e0]; if (e0 + 1 < E) d1 = (int)p[e0 + 1]; }
    } else {
        const int* p = (const int*)ei + E;
        if (pair) { int2 v = *(const int2*)(p + e0); d0 = v.x; d1 = v.y; }
        else { d0 = p[e0]; if (e0 + 1 < E) d1 = p[e0 + 1]; }
    }
    atomicAdd(&deg[d0], 1);
    if (d1 >= 0) atomicAdd(&deg[d1], 1);
}

// per-block (1024 nodes) degree sums
__global__ void blocksum_k(const int* __restrict__ deg, int* __restrict__ bsum,
                           int N) {
    __shared__ int ws[8];
    int t = threadIdx.x;                 // 256
    int i0 = blockIdx.x * 1024 + t * 4;
    int s = 0;
    if (i0 + 3 < N) {
        int4 v = *(const int4*)&deg[i0];
        s = v.x + v.y + v.z + v.w;
    } else {
        for (int j = 0; j < 4; ++j) if (i0 + j < N) s += deg[i0 + j];
    }
#pragma unroll
    for (int o = 16; o; o >>= 1) s += __shfl_down_sync(0xffffffffu, s, o);
    if ((t & 31) == 0) ws[t >> 5] = s;
    __syncthreads();
    if (t == 0) {
        int tot = 0;
#pragma unroll
        for (int i = 0; i < 8; ++i) tot += ws[i];
        bsum[blockIdx.x] = tot;
    }
}

// exclusive scan of ≤64 block sums; also zero BN stats for layer 1
__global__ void topscan_k(const int* __restrict__ bsum, int* __restrict__ bofs,
                          float* __restrict__ st, int nb) {
    int t = threadIdx.x;                 // 128
    st[t] = 0.f;
    __shared__ int sh[64];
    if (t < 64) {
        int lane = t & 31;
        int v = (t < nb) ? bsum[t] : 0;
        int inc = v;
#pragma unroll
        for (int o = 1; o < 32; o <<= 1) {
            int u = __shfl_up_sync(0xffffffffu, inc, o);
            if (lane >= o) inc += u;
        }
        sh[t] = inc;
    }
    __syncthreads();
    if (t < 64) {
        int add = (t >= 32) ? sh[31] : 0;
        int inc = sh[t] + add;
        int v = (t < nb) ? bsum[t] : 0;
        bofs[t] = inc - v;
    }
}

// per-block fill of off/cur via hierarchical scan; inserts self-loop at the
// head of each node's bucket and starts cur past it.
__global__ void fill_k(const int* __restrict__ deg, const int* __restrict__ bofs,
                       int* __restrict__ off, int* __restrict__ cur,
                       int* __restrict__ srcb, int N) {
    __shared__ int wsum[8];
    int t = threadIdx.x, lane = t & 31, warp = t >> 5;
    int i0 = blockIdx.x * 1024 + t * 4;
    int d0 = 0, d1 = 0, d2 = 0, d3 = 0;
    if (i0 + 3 < N) {
        int4 v = *(const int4*)&deg[i0];
        d0 = v.x; d1 = v.y; d2 = v.z; d3 = v.w;
    } else {
        if (i0     < N) d0 = deg[i0];
        if (i0 + 1 < N) d1 = deg[i0 + 1];
        if (i0 + 2 < N) d2 = deg[i0 + 2];
    }
    int tsum = d0 + d1 + d2 + d3;
    int inc = tsum;
#pragma unroll
    for (int o = 1; o < 32; o <<= 1) {
        int u = __shfl_up_sync(0xffffffffu, inc, o);
        if (lane >= o) inc += u;
    }
    if (lane == 31) wsum[warp] = inc;
    __syncthreads();
    int wofs = 0;
#pragma unroll
    for (int wi = 0; wi < 8; ++wi) if (wi < warp) wofs += wsum[wi];
    int base = bofs[blockIdx.x] + wofs + inc - tsum;
    int o0 = base, o1 = o0 + d0, o2 = o1 + d1, o3 = o2 + d2;
    if (i0 + 3 < N) {
        *(int4*)&off[i0] = make_int4(o0, o1, o2, o3);
        *(int4*)&cur[i0] = make_int4(o0 + 1, o1 + 1, o2 + 1, o3 + 1);
        srcb[o0] = i0;     srcb[o1] = i0 + 1;
        srcb[o2] = i0 + 2; srcb[o3] = i0 + 3;
    } else {
        if (i0     < N) { off[i0]     = o0; cur[i0]     = o0 + 1; srcb[o0] = i0; }
        if (i0 + 1 < N) { off[i0 + 1] = o1; cur[i0 + 1] = o1 + 1; srcb[o1] = i0 + 1; }
        if (i0 + 2 < N) { off[i0 + 2] = o2; cur[i0 + 2] = o2 + 1; srcb[o2] = i0 + 2; }
    }
}

// scatter REAL edges, 2 per thread
__global__ void scatter_k(const void* __restrict__ ei, int* __restrict__ cur,
                          int* __restrict__ srcb, int E) {
    int i = blockIdx.x * blockDim.x + threadIdx.x;
    int e0 = 2 * i;
    if (e0 >= E) return;
    int s0, s1 = -1, d0, d1 = -1;
    bool pair = ((E & 1) == 0) && (e0 + 1 < E);
    if (g_idx64) {
        const long long* ps = (const long long*)ei;
        const long long* pd = ps + E;
        if (pair) {
            longlong2 vs = *(const longlong2*)(ps + e0);
            longlong2 vd = *(const longlong2*)(pd + e0);
            s0 = (int)vs.x; s1 = (int)vs.y; d0 = (int)vd.x; d1 = (int)vd.y;
        } else {
            s0 = (int)ps[e0]; d0 = (int)pd[e0];
            if (e0 + 1 < E) { s1 = (int)ps[e0 + 1]; d1 = (int)pd[e0 + 1]; }
        }
    } else {
        const int* ps = (const int*)ei;
        const int* pd = ps + E;
        if (pair) {
            int2 vs = *(const int2*)(ps + e0);
            int2 vd = *(const int2*)(pd + e0);
            s0 = vs.x; s1 = vs.y; d0 = vd.x; d1 = vd.y;
        } else {
            s0 = ps[e0]; d0 = pd[e0];
            if (e0 + 1 < E) { s1 = ps[e0 + 1]; d1 = pd[e0 + 1]; }
        }
    }
    int pos = atomicAdd(&cur[d0], 1);
    srcb[pos] = s0;
    if (d1 >= 0) {
        int pos1 = atomicAdd(&cur[d1], 1);
        srcb[pos1] = s1;
    }
}

// ---------------- dual GEMM via tf32x3 tensor cores -------------------------
#define KC 16
__global__ void __launch_bounds__(256)
gemm_tf32(const float* __restrict__ A,
          const float* __restrict__ W0,
          const float* __restrict__ W1,
          const float* __restrict__ bnp,   // null = no BN
          float* __restrict__ O0, float* __restrict__ O1,
          int M, int K) {
    __shared__ uint32_t Ah[KC][136], Al[KC][136];
    __shared__ uint32_t Wh[KC][136], Wl[KC][136];
    const int t = threadIdx.x;
    const int lane = t & 31, warp = t >> 5;
    const int wm = warp >> 1, wn = warp & 1;
    const int g = lane >> 2, c = lane & 3;
    const int row0 = blockIdx.x * 128;
    const int rbase = wm * 32;
    const int nbase0 = wn * 64;

    float d[2][8][4];
#pragma unroll
    for (int i = 0; i < 2; ++i)
#pragma unroll
        for (int j = 0; j < 8; ++j)
#pragma unroll
            for (int q = 0; q < 4; ++q) d[i][j][q] = 0.f;

    const int nchunk = K / KC;
    for (int ch = 0; ch < nchunk; ++ch) {
        const int k0 = ch * KC;
        __syncthreads();
#pragma unroll
        for (int i = 0; i < 2; ++i) {
            int l = t + 256 * i;
            int r = l >> 2, kq = (l & 3) * 4;
            float4 v = make_float4(0.f, 0.f, 0.f, 0.f);
            if (row0 + r < M)
                v = *(const float4*)&A[(size_t)(row0 + r) * K + k0 + kq];
            if (bnp) {
                float4 sc = *(const float4*)&bnp[k0 + kq];
                float4 sh = *(const float4*)&bnp[64 + k0 + kq];
                v.x = fmaxf(v.x * sc.x + sh.x, 0.f);
                v.y = fmaxf(v.y * sc.y + sh.y, 0.f);
                v.z = fmaxf(v.z * sc.z + sh.z, 0.f);
                v.w = fmaxf(v.w * sc.w + sh.w, 0.f);
            }
            float vv[4] = {v.x, v.y, v.z, v.w};
#pragma unroll
            for (int j = 0; j < 4; ++j) {
                float hi = tf32r(vv[j]);
                float lo = tf32r(vv[j] - hi);
                Ah[kq + j][r] = __float_as_uint(hi);
                Al[kq + j][r] = __float_as_uint(lo);
            }
        }
#pragma unroll
        for (int i = 0; i < 2; ++i) {
            int l = t + 256 * i;
            int kk = l >> 5, col = (l & 31) * 4;
            const float* src = (col < 64)
                ? &W0[(size_t)(k0 + kk) * 64 + col]
                : &W1[(size_t)(k0 + kk) * 64 + (col - 64)];
            float4 v = *(const float4*)src;
            float vv[4] = {v.x, v.y, v.z, v.w};
#pragma unroll
            for (int j = 0; j < 4; ++j) {
                float hi = tf32r(vv[j]);
                float lo = tf32r(vv[j] - hi);
                Wh[kk][col + j] = __float_as_uint(hi);
                Wl[kk][col + j] = __float_as_uint(lo);
            }
        }
        __syncthreads();

#pragma unroll
        for (int ks = 0; ks < KC / 8; ++ks) {
            const int kb = ks * 8;
            uint32_t ah[2][4], al[2][4];
#pragma unroll
            for (int mt = 0; mt < 2; ++mt) {
                int r = rbase + mt * 16 + g;
                ah[mt][0] = Ah[kb + c][r];     ah[mt][1] = Ah[kb + c][r + 8];
                ah[mt][2] = Ah[kb + c + 4][r]; ah[mt][3] = Ah[kb + c + 4][r + 8];
                al[mt][0] = Al[kb + c][r];     al[mt][1] = Al[kb + c][r + 8];
                al[mt][2] = Al[kb + c + 4][r]; al[mt][3] = Al[kb + c + 4][r + 8];
            }
#pragma unroll
            for (int nt = 0; nt < 8; ++nt) {
                int n = nbase0 + nt * 8 + g;
                uint32_t bh0 = Wh[kb + c][n],     bh1 = Wh[kb + c + 4][n];
                uint32_t bl0 = Wl[kb + c][n],     bl1 = Wl[kb + c + 4][n];
#pragma unroll
                for (int mt = 0; mt < 2; ++mt) {
                    MMA_TF32(d[mt][nt], ah[mt], bh0, bh1);
                    MMA_TF32(d[mt][nt], ah[mt], bl0, bl1);
                    MMA_TF32(d[mt][nt], al[mt], bh0, bh1);
                }
            }
        }
    }

    float* O = (wn == 0) ? O0 : O1;
#pragma unroll
    for (int mt = 0; mt < 2; ++mt) {
#pragma unroll
        for (int nt = 0; nt < 8; ++nt) {
            int nn = nt * 8 + 2 * c;
            int r0w = row0 + rbase + mt * 16 + g;
            if (r0w < M)
                *(float2*)&O[(size_t)r0w * 64 + nn] =
                    make_float2(d[mt][nt][0], d[mt][nt][1]);
            int r1w = r0w + 8;
            if (r1w < M)
                *(float2*)&O[(size_t)r1w * 64 + nn] =
                    make_float2(d[mt][nt][2], d[mt][nt][3]);
        }
    }
}

// ---------------- fused GATv2 edge pass (node-parallel softmax, f32x2) ------
// 8 lanes per dst node (natural order → coalesced xr/agg), each lane owns
// 8 channels (4 packed f32x2 pairs). Halved per-lane register state vs the
// 4-lane version → ~2x occupancy and 2x warps → more gathers in flight
// (the kernel is L2-latency bound). leakyrelu(v) = 0.6v + 0.4|v| with
// pre-scaled att; plain exp softmax (scores bounded, self-loop anchors s).
// A/B double-buffered prefetch. Epilogue adds bias, writes agg, BN stats.
__global__ void gat_fused(const int* __restrict__ srcb,
                          const int* __restrict__ off,
                          const int* __restrict__ deg,
                          const float* __restrict__ xl,
                          const float* __restrict__ xr,
                          const float* __restrict__ att,
                          const float* __restrict__ bias,
                          float* __restrict__ agg,
                          float* __restrict__ st, int N) {
    __shared__ float ssum[64], ssq[64];
    const int t = threadIdx.x;
    int g = blockIdx.x * blockDim.x + t;
    int node = g >> 3;
    int lane = g & 7;
    bool valid = node < N;
    int nd = valid ? node : 0;

    // group mask: the 8 lanes of this node within the warp
    const unsigned gmask = 0xFFu << ((t & 31) & ~7);

    if (t < 64) { ssum[t] = 0.f; ssq[t] = 0.f; }

    // xr row slice (8 channels = 4 packed pairs)
    u64 rr[4];
    {
        const ulonglong2* p = (const ulonglong2*)(xr + (size_t)nd * 64) + lane * 2;
        ulonglong2 q0 = p[0], q1 = p[1];
        rr[0] = q0.x; rr[1] = q0.y; rr[2] = q1.x; rr[3] = q1.y;
    }
    // pre-scaled attention pairs
    u64 a06[4], a04[4];
    {
        const float* ap = att + lane * 8;
#pragma unroll
        for (int i = 0; i < 4; ++i) {
            float u = ap[2 * i], w = ap[2 * i + 1];
            a06[i] = fx_pack(0.6f * u, 0.6f * w);
            a04[i] = fx_pack(0.4f * u, 0.4f * w);
        }
    }

    int base = valid ? off[nd] : 0;
    int cnt  = valid ? deg[nd] : 0;

    float s = 0.f;
    u64 cc[4] = {0, 0, 0, 0};
    u64 A[4], B[4];

#define LOADE(BUF, IDX) do { \
        int _s = __ldg(&srcb[base + (IDX)]); \
        const ulonglong2* _p = (const ulonglong2*)(xl + (size_t)_s * 64) + lane * 2; \
        ulonglong2 _q0 = _p[0], _q1 = _p[1]; \
        BUF[0] = _q0.x; BUF[1] = _q0.y; BUF[2] = _q1.x; BUF[3] = _q1.y; } while(0)

#define PROC(BUF) do { \
        u64 e2 = 0; \
        _Pragma("unroll") \
        for (int _q = 0; _q < 4; ++_q) { \
            u64 v2 = fx_add(BUF[_q], rr[_q]); \
            e2 = fx_fma(a06[_q], v2, e2); \
            e2 = fx_fma(a04[_q], v2 & 0x7FFFFFFF7FFFFFFFULL, e2); \
        } \
        float2 eh = fx_unpack(e2); \
        float e = eh.x + eh.y; \
        e += __shfl_xor_sync(gmask, e, 1); \
        e += __shfl_xor_sync(gmask, e, 2); \
        e += __shfl_xor_sync(gmask, e, 4); \
        float pv = __expf(e); \
        s += pv; \
        u64 pp = fx_pack(pv, pv); \
        _Pragma("unroll") \
        for (int _q = 0; _q < 4; ++_q) cc[_q] = fx_fma(pp, BUF[_q], cc[_q]); } while(0)

    if (cnt > 0) LOADE(A, 0);
    int j = 0;
    for (; j + 2 <= cnt; j += 2) {
        LOADE(B, j + 1);
        PROC(A);
        if (j + 2 < cnt) LOADE(A, j + 2);
        PROC(B);
    }
    if (j < cnt) PROC(A);
#undef LOADE
#undef PROC

    float inv = 1.f / (s + 1e-16f);
    const float* bp = bias + lane * 8;
    float x[8];
#pragma unroll
    for (int q = 0; q < 4; ++q) {
        float2 cv = fx_unpack(cc[q]);
        x[2 * q]     = cv.x * inv + bp[2 * q];
        x[2 * q + 1] = cv.y * inv + bp[2 * q + 1];
    }

    if (valid) {
        float4* o = (float4*)(agg + (size_t)node * 64) + lane * 2;
        o[0] = make_float4(x[0], x[1], x[2], x[3]);
        o[1] = make_float4(x[4], x[5], x[6], x[7]);
    }
    if (!valid) {
#pragma unroll
        for (int i = 0; i < 8; ++i) x[i] = 0.f;
    }

    // BN stats: reduce over the 4 node-groups of this warp (full convergence),
    // then smem, then global.
    __syncthreads();   // ssum/ssq zero-init visible
#pragma unroll
    for (int i = 0; i < 8; ++i) {
        float sv = x[i];
        float qv = x[i] * x[i];
        sv += __shfl_down_sync(0xffffffffu, sv, 16);
        sv += __shfl_down_sync(0xffffffffu, sv, 8);
        qv += __shfl_down_sync(0xffffffffu, qv, 16);
        qv += __shfl_down_sync(0xffffffffu, qv, 8);
        if ((t & 31) < 8) {
            int ch = (t & 7) * 8 + i;
            atomicAdd(&ssum[ch], sv);
            atomicAdd(&ssq[ch], qv);
        }
    }
    __syncthreads();
    if (t < 64) {
        atomicAdd(&st[t], ssum[t]);
        atomicAdd(&st[64 + t], ssq[t]);
    }
}

// ---------------- BN prep: st -> (scale, shift); zero st for next layer -----
__global__ void prep_bn(const float* __restrict__ st,
                        const float* __restrict__ gamma,
                        const float* __restrict__ beta,
                        float* __restrict__ bnp,
                        float* __restrict__ st_mut, int N) {
    int t = threadIdx.x;   // 128 threads, 1 block
    float scale = 0.f, shift = 0.f;
    if (t < 64) {
        float invN = 1.f / (float)N;
        float mu  = st[t] * invN;
        float var = st[64 + t] * invN - mu * mu;
        float rs  = rsqrtf(var + 1e-5f);
        scale = gamma[t] * rs;
        shift = beta[t] - mu * scale;
    }
    __syncthreads();       // reads done before zeroing
    if (t < 64) { bnp[t] = scale; bnp[64 + t] = shift; }
    st_mut[t] = 0.f;
}

// ---------------- final head: BN(no affine) on [:,:32], softplus [:,32:] ----
__global__ void final_k(const float* __restrict__ v,
                        const float* __restrict__ st,
                        float* __restrict__ out, int N) {
    int i = blockIdx.x * blockDim.x + threadIdx.x;
    if (i >= N * 64) return;
    int n = i >> 6, c = i & 63;
    float x = v[i];
    if (c < 32) {
        float invN = 1.f / (float)N;
        float mu = st[c] * invN;
        float var = st[64 + c] * invN - mu * mu;
        out[(size_t)n * 32 + c] = (x - mu) * rsqrtf(var + 1e-5f);
    } else {
        float sp = fmaxf(x, 0.f) + log1pf(expf(-fabsf(x)));
        out[(size_t)N * 32 + (size_t)n * 32 + (c - 32)] = sp;
    }
}

// ---------------- host launcher ---------------------------------------------
extern "C" void kernel_launch(void* const* d_in, const int* in_sizes, int n_in,
                              void* d_out, int out_size) {
    const float* x    = (const float*)d_in[0];
    const void*  ei   = d_in[1];
    const float* Wl1  = (const float*)d_in[2];
    const float* Wr1  = (const float*)d_in[3];
    const float* att1 = (const float*)d_in[4];
    const float* b1   = (const float*)d_in[5];
    const float* ga1  = (const float*)d_in[6];
    const float* be1  = (const float*)d_in[7];
    const float* Wl2  = (const float*)d_in[8];
    const float* Wr2  = (const float*)d_in[9];
    const float* att2 = (const float*)d_in[10];
    const float* b2   = (const float*)d_in[11];
    float* out = (float*)d_out;

    const int N  = in_sizes[0] / 128;   // 50000
    const int E  = in_sizes[1] / 2;     // 800000

    float *p_xl, *p_xr, *p_agg, *p_st, *p_bnp;
    int *p_srcb, *p_off, *p_deg, *p_cur, *p_bsum, *p_bofs;
    cudaGetSymbolAddress((void**)&p_xl,   g_xl);
    cudaGetSymbolAddress((void**)&p_xr,   g_xr);
    cudaGetSymbolAddress((void**)&p_agg,  g_agg);
    cudaGetSymbolAddress((void**)&p_st,   g_st);
    cudaGetSymbolAddress((void**)&p_bnp,  g_bnp);
    cudaGetSymbolAddress((void**)&p_srcb, g_srcb);
    cudaGetSymbolAddress((void**)&p_off,  g_off);
    cudaGetSymbolAddress((void**)&p_deg,  g_deg);
    cudaGetSymbolAddress((void**)&p_cur,  g_cur);
    cudaGetSymbolAddress((void**)&p_bsum, g_bsum);
    cudaGetSymbolAddress((void**)&p_bofs, g_bofs);

    const int TB = 256;
    const int gEdge2 = ((E + 1) / 2 + TB - 1) / TB;   // 2 edges/thread
    const int gNode  = (N + TB - 1) / TB;
    const int gGemm  = (N + 127) / 128;
    const int gFuse  = (N * 8 + TB - 1) / TB;         // 8 lanes/node
    const int gElem  = (N * 64 + TB - 1) / TB;
    const int gScan  = (N + 1023) / 1024;     // 49 blocks

    // ---- CSR build (shared by both layers) ----
    zero_detect_k<<<gNode, TB>>>((const int*)ei, E, p_deg, N);
    hist_k<<<gEdge2, TB>>>(ei, p_deg, E);
    blocksum_k<<<gScan, TB>>>(p_deg, p_bsum, N);
    topscan_k<<<1, 128>>>(p_bsum, p_bofs, p_st, gScan);
    fill_k<<<gScan, TB>>>(p_deg, p_bofs, p_off, p_cur, p_srcb, N);
    scatter_k<<<gEdge2, TB>>>(ei, p_cur, p_srcb, E);

    // ---- layer 1 ----
    gemm_tf32<<<gGemm, TB>>>(x, Wl1, Wr1, nullptr, p_xl, p_xr, N, 128);
    gat_fused<<<gFuse, TB>>>(p_srcb, p_off, p_deg, p_xl, p_xr, att1, b1,
                             p_agg, p_st, N);
    prep_bn<<<1, 128>>>(p_st, ga1, be1, p_bnp, p_st, N);

    // ---- layer 2 (BN+ReLU fused into gemm A-staging) ----
    gemm_tf32<<<gGemm, TB>>>(p_agg, Wl2, Wr2, p_bnp, p_xl, p_xr, N, 64);
    gat_fused<<<gFuse, TB>>>(p_srcb, p_off, p_deg, p_xl, p_xr, att2, b2,
                             p_agg, p_st, N);
    final_k<<<gElem, TB>>>(p_agg, p_st, out, N);
}

// round 12
// speedup vs baseline: 1.4182x; 1.1052x over previous
#include <cuda_runtime.h>
#include <math.h>
#include <stdint.h>

// Problem constants (shapes fixed by the dataset)
#define NNODES 50000
#define NEDGES 800000
#define EETOT  (NNODES + NEDGES)
#define C64    64

typedef unsigned long long u64;

// ---------------- scratch (static device globals; no allocation allowed) ---
__device__ __align__(256) float g_xl [NNODES * C64];
__device__ __align__(256) float g_xr [NNODES * C64];
__device__ __align__(256) float g_agg[NNODES * C64];
__device__ __align__(256) int   g_srcb[EETOT];      // CSR src ids (sorted by dst)
__device__ __align__(256) int   g_off [NNODES];     // CSR row offsets
__device__ __align__(256) int   g_deg [NNODES];     // in-degree per node (incl self)
__device__ __align__(256) int   g_cur [NNODES];     // scatter cursors
__device__ __align__(256) int   g_bsum[64];         // per-block degree sums
__device__ __align__(256) int   g_bofs[64];         // exclusive scan of bsum
__device__ __align__(256) float g_st [128];         // per-channel sum / sumsq
__device__ __align__(256) float g_bnp[128];         // BN scale / shift
__device__ int g_idx64;                              // 1 if edge_index is int64

// ---------------- helpers ---------------------------------------------------
__device__ __forceinline__ float tf32r(float x) {
    uint32_t u;
    asm("cvt.rna.tf32.f32 %0, %1;" : "=r"(u) : "f"(x));
    return __uint_as_float(u);
}

__device__ __forceinline__ u64 fx_add(u64 a, u64 b) {
    u64 r; asm("add.rn.f32x2 %0,%1,%2;" : "=l"(r) : "l"(a), "l"(b)); return r;
}
__device__ __forceinline__ u64 fx_fma(u64 a, u64 b, u64 c) {
    u64 r; asm("fma.rn.f32x2 %0,%1,%2,%3;" : "=l"(r) : "l"(a), "l"(b), "l"(c)); return r;
}
__device__ __forceinline__ u64 fx_pack(float x, float y) {
    u64 r; asm("mov.b64 %0,{%1,%2};" : "=l"(r) : "f"(x), "f"(y)); return r;
}
__device__ __forceinline__ float2 fx_unpack(u64 a) {
    float x, y; asm("mov.b64 {%0,%1},%2;" : "=f"(x), "=f"(y) : "l"(a));
    return make_float2(x, y);
}

#define MMA_TF32(d, a, b0, b1) \
    asm volatile("mma.sync.aligned.m16n8k8.row.col.f32.tf32.tf32.f32 " \
                 "{%0,%1,%2,%3}, {%4,%5,%6,%7}, {%8,%9}, {%0,%1,%2,%3};" \
                 : "+f"((d)[0]), "+f"((d)[1]), "+f"((d)[2]), "+f"((d)[3]) \
                 : "r"((a)[0]), "r"((a)[1]), "r"((a)[2]), "r"((a)[3]), \
                   "r"(b0), "r"(b1))

// zero deg to 1 (self-loop pre-counted); block 0 warp 0 detects int64 vs int32
__global__ void zero_detect_k(const int* ei32, int E, int* __restrict__ deg,
                              int N) {
    int i = blockIdx.x * blockDim.x + threadIdx.x;
    if (i < N) deg[i] = 1;
    if (blockIdx.x == 0 && threadIdx.x < 32) {
        int t = threadIdx.x;
        int nz = 0;
        if (2 * t + 1 < 2 * E)        nz |= (ei32[2 * t + 1] != 0);
        if (2 * (t + 32) + 1 < 2 * E) nz |= (ei32[2 * (t + 32) + 1] != 0);
        nz = __any_sync(0xffffffffu, nz);
        if (t == 0) g_idx64 = nz ? 0 : 1;
    }
}

// ---------------- CSR build -------------------------------------------------
// histogram over REAL edges only (self-loops pre-counted), 4 edges/thread
__global__ void hist_k(const void* __restrict__ ei, int* __restrict__ deg,
                       int E) {
    int i = blockIdx.x * blockDim.x + threadIdx.x;
    int e0 = 4 * i;
    if (e0 >= E) return;
    int n = E - e0; if (n > 4) n = 4;
    int d[4];
    if (g_idx64) {
        const long long* p = (const long long*)ei + E;
        if (n == 4 && ((E & 1) == 0)) {
            longlong2 v0 = *(const longlong2*)(p + e0);
            longlong2 v1 = *(const longlong2*)(p + e0 + 2);
            d[0] = (int)v0.x; d[1] = (int)v0.y;
            d[2] = (int)v1.x; d[3] = (int)v1.y;
        } else for (int k = 0; k < n; ++k) d[k] = (int)p[e0 + k];
    } else {
        const int* p = (const int*)ei + E;
        if (n == 4 && ((E & 3) == 0)) {
            int4 v = *(const int4*)(p + e0);
            d[0] = v.x; d[1] = v.y; d[2] = v.z; d[3] = v.w;
        } else for (int k = 0; k < n; ++k) d[k] = p[e0 + k];
    }
#pragma unroll
    for (int k = 0; k < 4; ++k)
        if (k < n) atomicAdd(&deg[d[k]], 1);
}

// per-block (1024 nodes) degree sums
__global__ void blocksum_k(const int* __restrict__ deg, int* __restrict__ bsum,
                           int N) {
    __shared__ int ws[8];
    int t = threadIdx.x;                 // 256
    int i0 = blockIdx.x * 1024 + t * 4;
    int s = 0;
    if (i0 + 3 < N) {
        int4 v = *(const int4*)&deg[i0];
        s = v.x + v.y + v.z + v.w;
    } else {
        for (int j = 0; j < 4; ++j) if (i0 + j < N) s += deg[i0 + j];
    }
#pragma unroll
    for (int o = 16; o; o >>= 1) s += __shfl_down_sync(0xffffffffu, s, o);
    if ((t & 31) == 0) ws[t >> 5] = s;
    __syncthreads();
    if (t == 0) {
        int tot = 0;
#pragma unroll
        for (int i = 0; i < 8; ++i) tot += ws[i];
        bsum[blockIdx.x] = tot;
    }
}

// exclusive scan of ≤64 block sums; also zero BN stats for layer 1
__global__ void topscan_k(const int* __restrict__ bsum, int* __restrict__ bofs,
                          float* __restrict__ st, int nb) {
    int t = threadIdx.x;                 // 128
    st[t] = 0.f;
    __shared__ int sh[64];
    if (t < 64) {
        int lane = t & 31;
        int v = (t < nb) ? bsum[t] : 0;
        int inc = v;
#pragma unroll
        for (int o = 1; o < 32; o <<= 1) {
            int u = __shfl_up_sync(0xffffffffu, inc, o);
            if (lane >= o) inc += u;
        }
        sh[t] = inc;
    }
    __syncthreads();
    if (t < 64) {
        int add = (t >= 32) ? sh[31] : 0;
        int inc = sh[t] + add;
        int v = (t < nb) ? bsum[t] : 0;
        bofs[t] = inc - v;
    }
}

// per-block fill of off/cur via hierarchical scan; inserts self-loop at the
// head of each node's bucket and starts cur past it.
__global__ void fill_k(const int* __restrict__ deg, const int* __restrict__ bofs,
                       int* __restrict__ off, int* __restrict__ cur,
                       int* __restrict__ srcb, int N) {
    __shared__ int wsum[8];
    int t = threadIdx.x, lane = t & 31, warp = t >> 5;
    int i0 = blockIdx.x * 1024 + t * 4;
    int d0 = 0, d1 = 0, d2 = 0, d3 = 0;
    if (i0 + 3 < N) {
        int4 v = *(const int4*)&deg[i0];
        d0 = v.x; d1 = v.y; d2 = v.z; d3 = v.w;
    } else {
        if (i0     < N) d0 = deg[i0];
        if (i0 + 1 < N) d1 = deg[i0 + 1];
        if (i0 + 2 < N) d2 = deg[i0 + 2];
    }
    int tsum = d0 + d1 + d2 + d3;
    int inc = tsum;
#pragma unroll
    for (int o = 1; o < 32; o <<= 1) {
        int u = __shfl_up_sync(0xffffffffu, inc, o);
        if (lane >= o) inc += u;
    }
    if (lane == 31) wsum[warp] = inc;
    __syncthreads();
    int wofs = 0;
#pragma unroll
    for (int wi = 0; wi < 8; ++wi) if (wi < warp) wofs += wsum[wi];
    int base = bofs[blockIdx.x] + wofs + inc - tsum;
    int o0 = base, o1 = o0 + d0, o2 = o1 + d1, o3 = o2 + d2;
    if (i0 + 3 < N) {
        *(int4*)&off[i0] = make_int4(o0, o1, o2, o3);
        *(int4*)&cur[i0] = make_int4(o0 + 1, o1 + 1, o2 + 1, o3 + 1);
        srcb[o0] = i0;     srcb[o1] = i0 + 1;
        srcb[o2] = i0 + 2; srcb[o3] = i0 + 3;
    } else {
        if (i0     < N) { off[i0]     = o0; cur[i0]     = o0 + 1; srcb[o0] = i0; }
        if (i0 + 1 < N) { off[i0 + 1] = o1; cur[i0 + 1] = o1 + 1; srcb[o1] = i0 + 1; }
        if (i0 + 2 < N) { off[i0 + 2] = o2; cur[i0 + 2] = o2 + 1; srcb[o2] = i0 + 2; }
    }
}

// scatter REAL edges, 4 per thread
__global__ void scatter_k(const void* __restrict__ ei, int* __restrict__ cur,
                          int* __restrict__ srcb, int E) {
    int i = blockIdx.x * blockDim.x + threadIdx.x;
    int e0 = 4 * i;
    if (e0 >= E) return;
    int n = E - e0; if (n > 4) n = 4;
    int s[4], d[4];
    if (g_idx64) {
        const long long* ps = (const long long*)ei;
        const long long* pd = ps + E;
        if (n == 4 && ((E & 1) == 0)) {
            longlong2 v0 = *(const longlong2*)(ps + e0);
            longlong2 v1 = *(const longlong2*)(ps + e0 + 2);
            longlong2 w0 = *(const longlong2*)(pd + e0);
            longlong2 w1 = *(const longlong2*)(pd + e0 + 2);
            s[0] = (int)v0.x; s[1] = (int)v0.y; s[2] = (int)v1.x; s[3] = (int)v1.y;
            d[0] = (int)w0.x; d[1] = (int)w0.y; d[2] = (int)w1.x; d[3] = (int)w1.y;
        } else for (int k = 0; k < n; ++k) {
            s[k] = (int)ps[e0 + k]; d[k] = (int)pd[e0 + k];
        }
    } else {
        const int* ps = (const int*)ei;
        const int* pd = ps + E;
        if (n == 4 && ((E & 3) == 0)) {
            int4 v = *(const int4*)(ps + e0);
            int4 w = *(const int4*)(pd + e0);
            s[0] = v.x; s[1] = v.y; s[2] = v.z; s[3] = v.w;
            d[0] = w.x; d[1] = w.y; d[2] = w.z; d[3] = w.w;
        } else for (int k = 0; k < n; ++k) {
            s[k] = ps[e0 + k]; d[k] = pd[e0 + k];
        }
    }
#pragma unroll
    for (int k = 0; k < 4; ++k)
        if (k < n) {
            int pos = atomicAdd(&cur[d[k]], 1);
            srcb[pos] = s[k];
        }
}

// ---------------- dual GEMM via tf32x3 tensor cores -------------------------
#define KC 16
__global__ void __launch_bounds__(256)
gemm_tf32(const float* __restrict__ A,
          const float* __restrict__ W0,
          const float* __restrict__ W1,
          const float* __restrict__ bnp,   // null = no BN
          float* __restrict__ O0, float* __restrict__ O1,
          int M, int K) {
    __shared__ uint32_t Ah[KC][136], Al[KC][136];
    __shared__ uint32_t Wh[KC][136], Wl[KC][136];
    const int t = threadIdx.x;
    const int lane = t & 31, warp = t >> 5;
    const int wm = warp >> 1, wn = warp & 1;
    const int g = lane >> 2, c = lane & 3;
    const int row0 = blockIdx.x * 128;
    const int rbase = wm * 32;
    const int nbase0 = wn * 64;

    float d[2][8][4];
#pragma unroll
    for (int i = 0; i < 2; ++i)
#pragma unroll
        for (int j = 0; j < 8; ++j)
#pragma unroll
            for (int q = 0; q < 4; ++q) d[i][j][q] = 0.f;

    const int nchunk = K / KC;
    for (int ch = 0; ch < nchunk; ++ch) {
        const int k0 = ch * KC;
        __syncthreads();
#pragma unroll
        for (int i = 0; i < 2; ++i) {
            int l = t + 256 * i;
            int r = l >> 2, kq = (l & 3) * 4;
            float4 v = make_float4(0.f, 0.f, 0.f, 0.f);
            if (row0 + r < M)
                v = *(const float4*)&A[(size_t)(row0 + r) * K + k0 + kq];
            if (bnp) {
                float4 sc = *(const float4*)&bnp[k0 + kq];
                float4 sh = *(const float4*)&bnp[64 + k0 + kq];
                v.x = fmaxf(v.x * sc.x + sh.x, 0.f);
                v.y = fmaxf(v.y * sc.y + sh.y, 0.f);
                v.z = fmaxf(v.z * sc.z + sh.z, 0.f);
                v.w = fmaxf(v.w * sc.w + sh.w, 0.f);
            }
            float vv[4] = {v.x, v.y, v.z, v.w};
#pragma unroll
            for (int j = 0; j < 4; ++j) {
                float hi = tf32r(vv[j]);
                float lo = tf32r(vv[j] - hi);
                Ah[kq + j][r] = __float_as_uint(hi);
                Al[kq + j][r] = __float_as_uint(lo);
            }
        }
#pragma unroll
        for (int i = 0; i < 2; ++i) {
            int l = t + 256 * i;
            int kk = l >> 5, col = (l & 31) * 4;
            const float* src = (col < 64)
                ? &W0[(size_t)(k0 + kk) * 64 + col]
                : &W1[(size_t)(k0 + kk) * 64 + (col - 64)];
            float4 v = *(const float4*)src;
            float vv[4] = {v.x, v.y, v.z, v.w};
#pragma unroll
            for (int j = 0; j < 4; ++j) {
                float hi = tf32r(vv[j]);
                float lo = tf32r(vv[j] - hi);
                Wh[kk][col + j] = __float_as_uint(hi);
                Wl[kk][col + j] = __float_as_uint(lo);
            }
        }
        __syncthreads();

#pragma unroll
        for (int ks = 0; ks < KC / 8; ++ks) {
            const int kb = ks * 8;
            uint32_t ah[2][4], al[2][4];
#pragma unroll
            for (int mt = 0; mt < 2; ++mt) {
                int r = rbase + mt * 16 + g;
                ah[mt][0] = Ah[kb + c][r];     ah[mt][1] = Ah[kb + c][r + 8];
                ah[mt][2] = Ah[kb + c + 4][r]; ah[mt][3] = Ah[kb + c + 4][r + 8];
                al[mt][0] = Al[kb + c][r];     al[mt][1] = Al[kb + c][r + 8];
                al[mt][2] = Al[kb + c + 4][r]; al[mt][3] = Al[kb + c + 4][r + 8];
            }
#pragma unroll
            for (int nt = 0; nt < 8; ++nt) {
                int n = nbase0 + nt * 8 + g;
                uint32_t bh0 = Wh[kb + c][n],     bh1 = Wh[kb + c + 4][n];
                uint32_t bl0 = Wl[kb + c][n],     bl1 = Wl[kb + c + 4][n];
#pragma unroll
                for (int mt = 0; mt < 2; ++mt) {
                    MMA_TF32(d[mt][nt], ah[mt], bh0, bh1);
                    MMA_TF32(d[mt][nt], ah[mt], bl0, bl1);
                    MMA_TF32(d[mt][nt], al[mt], bh0, bh1);
                }
            }
        }
    }

    float* O = (wn == 0) ? O0 : O1;
#pragma unroll
    for (int mt = 0; mt < 2; ++mt) {
#pragma unroll
        for (int nt = 0; nt < 8; ++nt) {
            int nn = nt * 8 + 2 * c;
            int r0w = row0 + rbase + mt * 16 + g;
            if (r0w < M)
                *(float2*)&O[(size_t)r0w * 64 + nn] =
                    make_float2(d[mt][nt][0], d[mt][nt][1]);
            int r1w = r0w + 8;
            if (r1w < M)
                *(float2*)&O[(size_t)r1w * 64 + nn] =
                    make_float2(d[mt][nt][2], d[mt][nt][3]);
        }
    }
}

// ---------------- fused GATv2 edge pass (node-parallel softmax, f32x2) ------
// 8 lanes per dst node (natural order → coalesced xr/agg), each lane owns
// 8 channels (4 packed f32x2 pairs). leakyrelu(v) = 0.6v + 0.4|v| with
// pre-scaled att; plain exp softmax (scores bounded, self-loop anchors s).
// A/B double-buffered prefetch. Epilogue adds bias, writes agg, BN stats.
__global__ void gat_fused(const int* __restrict__ srcb,
                          const int* __restrict__ off,
                          const int* __restrict__ deg,
                          const float* __restrict__ xl,
                          const float* __restrict__ xr,
                          const float* __restrict__ att,
                          const float* __restrict__ bias,
                          float* __restrict__ agg,
                          float* __restrict__ st, int N) {
    __shared__ float ssum[64], ssq[64];
    const int t = threadIdx.x;
    int g = blockIdx.x * blockDim.x + t;
    int node = g >> 3;
    int lane = g & 7;
    bool valid = node < N;
    int nd = valid ? node : 0;

    const unsigned gmask = 0xFFu << ((t & 31) & ~7);

    if (t < 64) { ssum[t] = 0.f; ssq[t] = 0.f; }

    u64 rr[4];
    {
        const ulonglong2* p = (const ulonglong2*)(xr + (size_t)nd * 64) + lane * 2;
        ulonglong2 q0 = p[0], q1 = p[1];
        rr[0] = q0.x; rr[1] = q0.y; rr[2] = q1.x; rr[3] = q1.y;
    }
    u64 a06[4], a04[4];
    {
        const float* ap = att + lane * 8;
#pragma unroll
        for (int i = 0; i < 4; ++i) {
            float u = ap[2 * i], w = ap[2 * i + 1];
            a06[i] = fx_pack(0.6f * u, 0.6f * w);
            a04[i] = fx_pack(0.4f * u, 0.4f * w);
        }
    }

    int base = valid ? off[nd] : 0;
    int cnt  = valid ? deg[nd] : 0;

    float s = 0.f;
    u64 cc[4] = {0, 0, 0, 0};
    u64 A[4], B[4];

#define LOADE(BUF, IDX) do { \
        int _s = __ldg(&srcb[base + (IDX)]); \
        const ulonglong2* _p = (const ulonglong2*)(xl + (size_t)_s * 64) + lane * 2; \
        ulonglong2 _q0 = _p[0], _q1 = _p[1]; \
        BUF[0] = _q0.x; BUF[1] = _q0.y; BUF[2] = _q1.x; BUF[3] = _q1.y; } while(0)

#define PROC(BUF) do { \
        u64 e2 = 0; \
        _Pragma("unroll") \
        for (int _q = 0; _q < 4; ++_q) { \
            u64 v2 = fx_add(BUF[_q], rr[_q]); \
            e2 = fx_fma(a06[_q], v2, e2); \
            e2 = fx_fma(a04[_q], v2 & 0x7FFFFFFF7FFFFFFFULL, e2); \
        } \
        float2 eh = fx_unpack(e2); \
        float e = eh.x + eh.y; \
        e += __shfl_xor_sync(gmask, e, 1); \
        e += __shfl_xor_sync(gmask, e, 2); \
        e += __shfl_xor_sync(gmask, e, 4); \
        float pv = __expf(e); \
        s += pv; \
        u64 pp = fx_pack(pv, pv); \
        _Pragma("unroll") \
        for (int _q = 0; _q < 4; ++_q) cc[_q] = fx_fma(pp, BUF[_q], cc[_q]); } while(0)

    if (cnt > 0) LOADE(A, 0);
    int j = 0;
    for (; j + 2 <= cnt; j += 2) {
        LOADE(B, j + 1);
        PROC(A);
        if (j + 2 < cnt) LOADE(A, j + 2);
        PROC(B);
    }
    if (j < cnt) PROC(A);
#undef LOADE
#undef PROC

    float inv = 1.f / (s + 1e-16f);
    const float* bp = bias + lane * 8;
    float x[8];
#pragma unroll
    for (int q = 0; q < 4; ++q) {
        float2 cv = fx_unpack(cc[q]);
        x[2 * q]     = cv.x * inv + bp[2 * q];
        x[2 * q + 1] = cv.y * inv + bp[2 * q + 1];
    }

    if (valid) {
        float4* o = (float4*)(agg + (size_t)node * 64) + lane * 2;
        o[0] = make_float4(x[0], x[1], x[2], x[3]);
        o[1] = make_float4(x[4], x[5], x[6], x[7]);
    }
    if (!valid) {
#pragma unroll
        for (int i = 0; i < 8; ++i) x[i] = 0.f;
    }

    __syncthreads();   // ssum/ssq zero-init visible
#pragma unroll
    for (int i = 0; i < 8; ++i) {
        float sv = x[i];
        float qv = x[i] * x[i];
        sv += __shfl_down_sync(0xffffffffu, sv, 16);
        sv += __shfl_down_sync(0xffffffffu, sv, 8);
        qv += __shfl_down_sync(0xffffffffu, qv, 16);
        qv += __shfl_down_sync(0xffffffffu, qv, 8);
        if ((t & 31) < 8) {
            int ch = (t & 7) * 8 + i;
            atomicAdd(&ssum[ch], sv);
            atomicAdd(&ssq[ch], qv);
        }
    }
    __syncthreads();
    if (t < 64) {
        atomicAdd(&st[t], ssum[t]);
        atomicAdd(&st[64 + t], ssq[t]);
    }
}

// ---------------- BN prep: st -> (scale, shift); zero st for next layer -----
__global__ void prep_bn(const float* __restrict__ st,
                        const float* __restrict__ gamma,
                        const float* __restrict__ beta,
                        float* __restrict__ bnp,
                        float* __restrict__ st_mut, int N) {
    int t = threadIdx.x;   // 128 threads, 1 block
    float scale = 0.f, shift = 0.f;
    if (t < 64) {
        float invN = 1.f / (float)N;
        float mu  = st[t] * invN;
        float var = st[64 + t] * invN - mu * mu;
        float rs  = rsqrtf(var + 1e-5f);
        scale = gamma[t] * rs;
        shift = beta[t] - mu * scale;
    }
    __syncthreads();       // reads done before zeroing
    if (t < 64) { bnp[t] = scale; bnp[64 + t] = shift; }
    st_mut[t] = 0.f;
}

// ---------------- final head: BN(no affine) on [:,:32], softplus [:,32:] ----
__global__ void final_k(const float* __restrict__ v,
                        const float* __restrict__ st,
                        float* __restrict__ out, int N) {
    int i = blockIdx.x * blockDim.x + threadIdx.x;
    if (i >= N * 64) return;
    int n = i >> 6, c = i & 63;
    float x = v[i];
    if (c < 32) {
        float invN = 1.f / (float)N;
        float mu = st[c] * invN;
        float var = st[64 + c] * invN - mu * mu;
        out[(size_t)n * 32 + c] = (x - mu) * rsqrtf(var + 1e-5f);
    } else {
        float sp = fmaxf(x, 0.f) + log1pf(expf(-fabsf(x)));
        out[(size_t)N * 32 + (size_t)n * 32 + (c - 32)] = sp;
    }
}

// ---------------- host launcher ---------------------------------------------
extern "C" void kernel_launch(void* const* d_in, const int* in_sizes, int n_in,
                              void* d_out, int out_size) {
    const float* x    = (const float*)d_in[0];
    const void*  ei   = d_in[1];
    const float* Wl1  = (const float*)d_in[2];
    const float* Wr1  = (const float*)d_in[3];
    const float* att1 = (const float*)d_in[4];
    const float* b1   = (const float*)d_in[5];
    const float* ga1  = (const float*)d_in[6];
    const float* be1  = (const float*)d_in[7];
    const float* Wl2  = (const float*)d_in[8];
    const float* Wr2  = (const float*)d_in[9];
    const float* att2 = (const float*)d_in[10];
    const float* b2   = (const float*)d_in[11];
    float* out = (float*)d_out;

    const int N  = in_sizes[0] / 128;   // 50000
    const int E  = in_sizes[1] / 2;     // 800000

    float *p_xl, *p_xr, *p_agg, *p_st, *p_bnp;
    int *p_srcb, *p_off, *p_deg, *p_cur, *p_bsum, *p_bofs;
    cudaGetSymbolAddress((void**)&p_xl,   g_xl);
    cudaGetSymbolAddress((void**)&p_xr,   g_xr);
    cudaGetSymbolAddress((void**)&p_agg,  g_agg);
    cudaGetSymbolAddress((void**)&p_st,   g_st);
    cudaGetSymbolAddress((void**)&p_bnp,  g_bnp);
    cudaGetSymbolAddress((void**)&p_srcb, g_srcb);
    cudaGetSymbolAddress((void**)&p_off,  g_off);
    cudaGetSymbolAddress((void**)&p_deg,  g_deg);
    cudaGetSymbolAddress((void**)&p_cur,  g_cur);
    cudaGetSymbolAddress((void**)&p_bsum, g_bsum);
    cudaGetSymbolAddress((void**)&p_bofs, g_bofs);

    // fork/join stream for gemm1 || CSR build (created once; lazy init
    // happens on the uncaptured correctness call)
    static cudaStream_t s1 = nullptr;
    static cudaEvent_t evFork = nullptr, evJoin = nullptr;
    static bool tried = false;
    if (!tried) {
        tried = true;
        if (cudaStreamCreateWithFlags(&s1, cudaStreamNonBlocking) != cudaSuccess)
            s1 = nullptr;
        if (s1) {
            if (cudaEventCreateWithFlags(&evFork, cudaEventDisableTiming) != cudaSuccess ||
                cudaEventCreateWithFlags(&evJoin, cudaEventDisableTiming) != cudaSuccess) {
                s1 = nullptr;
            }
        }
    }

    const int TB = 256;
    const int gEdge4 = ((E + 3) / 4 + TB - 1) / TB;   // 4 edges/thread
    const int gNode  = (N + TB - 1) / TB;
    const int gGemm  = (N + 127) / 128;
    const int gFuse  = (N * 8 + TB - 1) / TB;         // 8 lanes/node
    const int gElem  = (N * 64 + TB - 1) / TB;
    const int gScan  = (N + 1023) / 1024;     // 49 blocks

    // ---- fork: gemm1 (independent of CSR) on s1 ----
    if (s1) {
        cudaEventRecord(evFork, 0);
        cudaStreamWaitEvent(s1, evFork, 0);
        gemm_tf32<<<gGemm, TB, 0, s1>>>(x, Wl1, Wr1, nullptr, p_xl, p_xr, N, 128);
    } else {
        gemm_tf32<<<gGemm, TB>>>(x, Wl1, Wr1, nullptr, p_xl, p_xr, N, 128);
    }

    // ---- CSR build on the main stream ----
    zero_detect_k<<<gNode, TB>>>((const int*)ei, E, p_deg, N);
    hist_k<<<gEdge4, TB>>>(ei, p_deg, E);
    blocksum_k<<<gScan, TB>>>(p_deg, p_bsum, N);
    topscan_k<<<1, 128>>>(p_bsum, p_bofs, p_st, gScan);
    fill_k<<<gScan, TB>>>(p_deg, p_bofs, p_off, p_cur, p_srcb, N);
    scatter_k<<<gEdge4, TB>>>(ei, p_cur, p_srcb, E);

    // ---- join ----
    if (s1) {
        cudaEventRecord(evJoin, s1);
        cudaStreamWaitEvent(0, evJoin, 0);
    }

    // ---- layer 1 ----
    gat_fused<<<gFuse, TB>>>(p_srcb, p_off, p_deg, p_xl, p_xr, att1, b1,
                             p_agg, p_st, N);
    prep_bn<<<1, 128>>>(p_st, ga1, be1, p_bnp, p_st, N);

    // ---- layer 2 (BN+ReLU fused into gemm A-staging) ----
    gemm_tf32<<<gGemm, TB>>>(p_agg, Wl2, Wr2, p_bnp, p_xl, p_xr, N, 64);
    gat_fused<<<gFuse, TB>>>(p_srcb, p_off, p_deg, p_xl, p_xr, att2, b2,
                             p_agg, p_st, N);
    final_k<<<gElem, TB>>>(p_agg, p_st, out, N);
}